// round 7
// baseline (speedup 1.0000x reference)
#include <cuda_runtime.h>
#include <cstdint>
#include <cstddef>

#define BB   8
#define NPTS 4096
#define SS   2048
#define KNB  64
#define CIN  64
#define HID  128
#define BSZ  (BB*SS)
#define R2F  0.04f
#define MAXC 1024
#define NBLK (BSZ/2)          // 2 centroids per GEMM block

// ---------------- device scratch ----------------
__device__ float  g_ctr[BSZ*3];
__device__ int    g_nbr[BSZ*KNB];
__device__ int    g_cnt[BSZ];
__device__ float4 g_pos4[BB*NPTS];
__device__ float  g_H0[(size_t)BSZ*KNB*HID];
__device__ float  g_H1[(size_t)BSZ*KNB*HID];
__device__ double g_stat[2][2][32][HID];
__device__ float  g_scale[2][HID];
__device__ float  g_shift[2][HID];
// fragment-ordered tf32 hi/lo weights: per slab 8192 floats = [h][kk][tt][lane][reg]
__device__ float  g_WF0[3*8192];
__device__ float  g_WF1[4*8192];
__device__ float  g_WF2[4*8192];

// ---------------- helpers ----------------
__device__ __forceinline__ float2 tf32_split(float v) {
    unsigned uh, ul;
    asm("cvt.rna.tf32.f32 %0, %1;" : "=r"(uh) : "f"(v));
    float h = __uint_as_float(uh);
    asm("cvt.rna.tf32.f32 %0, %1;" : "=r"(ul) : "f"(v - h));
    return make_float2(h, __uint_as_float(ul));
}

__device__ __forceinline__ void mma8(float* c, float4 a, float2 b) {
    asm volatile("mma.sync.aligned.m16n8k8.row.col.f32.tf32.tf32.f32 "
        "{%0,%1,%2,%3}, {%4,%5,%6,%7}, {%8,%9}, {%0,%1,%2,%3};\n"
        : "+f"(c[0]), "+f"(c[1]), "+f"(c[2]), "+f"(c[3])
        : "r"(__float_as_uint(a.x)), "r"(__float_as_uint(a.y)),
          "r"(__float_as_uint(a.z)), "r"(__float_as_uint(a.w)),
          "r"(__float_as_uint(b.x)), "r"(__float_as_uint(b.y)));
}

// write one A element (row m of 128, col j of slab) into hi/lo fragment arrays
__device__ __forceinline__ void putA(float* sAh, float* sAl, int m, int j, float v) {
    int rr = m & 15, f = m >> 4;
    int kk = j >> 3, cc = j & 7;
    int idx = ((kk*8 + f)*32 + (rr&7)*4 + (cc&3))*4 + (rr>>3) + 2*(cc>>2);
    float2 hl = tf32_split(v);
    sAh[idx] = hl.x; sAl[idx] = hl.y;
}

// ---------------- zero stats ----------------
__global__ void k_zero() {
    int i = blockIdx.x * blockDim.x + threadIdx.x;
    const int n = 2*2*32*HID;
    double* p = &g_stat[0][0][0][0];
    for (; i < n; i += gridDim.x * blockDim.x) p[i] = 0.0;
}

// ---------------- pos -> float4 ----------------
__global__ void k_pos4(const float* __restrict__ pos) {
    int i = blockIdx.x * blockDim.x + threadIdx.x;
    if (i < BB*NPTS)
        g_pos4[i] = make_float4(pos[3*i], pos[3*i+1], pos[3*i+2], 0.f);
}

// ---------------- weight fragment prep (tf32 hi/lo) ----------------
// dst selected by tag in DEVICE code (passing __device__ symbols from host is UB)
__global__ void k_wprep(const float* __restrict__ W, int K, int nslab, int which) {
    float* dst = (which == 0) ? g_WF0 : (which == 1) ? g_WF1 : g_WF2;
    int i = blockIdx.x * blockDim.x + threadIdx.x;
    int tot = nslab * 4096;
    if (i >= tot) return;
    int s = i >> 12, r = i & 4095;
    int reg = r & 1, lane = (r >> 1) & 31, tt = (r >> 6) & 15, kk = (r >> 10) & 3;
    int k = s*32 + kk*8 + reg*4 + (lane & 3);
    int n = tt*8 + (lane >> 2);
    float v = (k < K) ? W[k*HID + n] : 0.f;
    float2 hl = tf32_split(v);
    dst[s*8192 + r]        = hl.x;
    dst[s*8192 + 4096 + r] = hl.y;
}

// ---------------- farthest point sampling (known-good) ----------------
__global__ void __launch_bounds__(1024) k_fps(const float* __restrict__ pos,
                                              float* __restrict__ octr,
                                              float* __restrict__ obat) {
    int b = blockIdx.x, t = threadIdx.x;
    const float* p = pos + (size_t)b * NPTS * 3;
    float px[4], py[4], pz[4], md[4];
#pragma unroll
    for (int j = 0; j < 4; j++) {
        int i = t + j * 1024;
        px[j] = p[3*i]; py[j] = p[3*i+1]; pz[j] = p[3*i+2];
        md[j] = __int_as_float(0x7f800000);
    }
    __shared__ float sv[32];
    __shared__ int   si[32];
    __shared__ int   sLast;
    int lane = t & 31, w = t >> 5;
    int last = 0;
    for (int s = 0; s < SS; s++) {
        float qx = p[3*last], qy = p[3*last+1], qz = p[3*last+2];
        if (t == 0) {
            int o = b*SS + s;
            g_ctr[o*3] = qx; g_ctr[o*3+1] = qy; g_ctr[o*3+2] = qz;
            if (octr) { octr[o*3] = qx; octr[o*3+1] = qy; octr[o*3+2] = qz; }
            if (obat) obat[o] = (float)b;
        }
        float bv = -1.f; int bi = 0;
#pragma unroll
        for (int j = 0; j < 4; j++) {
            float dx = px[j]-qx, dy = py[j]-qy, dz = pz[j]-qz;
            float d = fmaf(dz, dz, fmaf(dy, dy, __fmul_rn(dx, dx)));
            md[j] = fminf(md[j], d);
            if (md[j] > bv) { bv = md[j]; bi = t + j*1024; }
        }
#pragma unroll
        for (int off = 16; off > 0; off >>= 1) {
            float ov = __shfl_down_sync(0xffffffffu, bv, off);
            int   oi = __shfl_down_sync(0xffffffffu, bi, off);
            if (ov > bv || (ov == bv && oi < bi)) { bv = ov; bi = oi; }
        }
        if (lane == 0) { sv[w] = bv; si[w] = bi; }
        __syncthreads();
        if (w == 0) {
            bv = sv[lane]; bi = si[lane];
#pragma unroll
            for (int off = 16; off > 0; off >>= 1) {
                float ov = __shfl_down_sync(0xffffffffu, bv, off);
                int   oi = __shfl_down_sync(0xffffffffu, bi, off);
                if (ov > bv || (ov == bv && oi < bi)) { bv = ov; bi = oi; }
            }
            if (lane == 0) sLast = bi;
        }
        __syncthreads();
        last = sLast;
    }
}

// ---------------- radius-capped kNN (known-good) ----------------
__global__ void __launch_bounds__(128) k_nbr() {
    int c = blockIdx.x, t = threadIdx.x;
    int b = c >> 11;
    __shared__ float sd[MAXC];
    __shared__ int   sid[MAXC];
    __shared__ int   hist[128];
    __shared__ int   sc, so, s_tb, s_m, tc;
    __shared__ float td[256];
    __shared__ int   tdi[256];
    __shared__ int   wtot[4];
    if (t == 0) { sc = 0; so = 0; tc = 0; }
    hist[t] = 0;
    float cx = g_ctr[c*3], cy = g_ctr[c*3+1], cz = g_ctr[c*3+2];
    __syncthreads();
    for (int i = t; i < NPTS; i += 128) {
        float4 P = g_pos4[b*NPTS + i];
        float dx = P.x-cx, dy = P.y-cy, dz = P.z-cz;
        float d = fmaf(dz, dz, fmaf(dy, dy, __fmul_rn(dx, dx)));
        if (d <= R2F) {
            int k = atomicAdd(&sc, 1);
            if (k < MAXC) { sd[k] = d; sid[k] = i; }
        }
    }
    __syncthreads();
    int cnt = min(sc, MAXC);
    if (cnt <= KNB) {
        if (t < cnt) g_nbr[c*KNB + t] = sid[t];
        if (t == 0) g_cnt[c] = cnt;
        return;
    }
    const float bsc = 128.0f / R2F;
    for (int i = t; i < cnt; i += 128) {
        int bk = min(127, (int)(sd[i] * bsc));
        atomicAdd(&hist[bk], 1);
    }
    __syncthreads();
    {
        int lane = t & 31, w = t >> 5;
        int h = hist[t], v = h;
#pragma unroll
        for (int o = 1; o < 32; o <<= 1) {
            int u = __shfl_up_sync(0xffffffffu, v, o);
            if (lane >= o) v += u;
        }
        if (lane == 31) wtot[w] = v;
        __syncthreads();
        int base = 0;
        for (int k2 = 0; k2 < w; k2++) base += wtot[k2];
        int incl = v + base, excl = incl - h;
        if (incl >= KNB && excl < KNB) { s_tb = t; s_m = excl; }
    }
    __syncthreads();
    int tb = s_tb, m = s_m;
    for (int i = t; i < cnt; i += 128) {
        int bk = min(127, (int)(sd[i] * bsc));
        if (bk < tb) {
            int k = atomicAdd(&so, 1);
            g_nbr[c*KNB + k] = sid[i];
        } else if (bk == tb) {
            int k = atomicAdd(&tc, 1);
            if (k < 256) { td[k] = sd[i]; tdi[k] = sid[i]; }
        }
    }
    __syncthreads();
    int bn = min(tc, 256), rem = KNB - m;
    for (int i = t; i < bn; i += 128) {
        float di = td[i]; int ii = tdi[i];
        int rank = 0;
        for (int j2 = 0; j2 < bn; j2++) {
            float dj = td[j2]; int ij = tdi[j2];
            if (dj < di || (dj == di && ij < ii)) rank++;
        }
        if (rank < rem) {
            int k = atomicAdd(&so, 1);
            g_nbr[c*KNB + k] = tdi[i];
        }
    }
    if (t == 0) g_cnt[c] = KNB;
}

// acc layout: acc[fl][tt][reg], reg=rh*2+rr ; row m = 32w+16fl+8rh+g ; col n = tt*8+tig*2+rr

// ---------------- layer 0 GEMM (K padded 67->72, slabs {32,32,8}) ----------------
__global__ void __launch_bounds__(128) k_l0(const float* __restrict__ x,
                                            const float* __restrict__ b0) {
    extern __shared__ float sm[];
    float* sAh   = sm;
    float* sAl   = sm + 4096;
    float* sBh   = sm + 8192;
    float* sBl   = sm + 12288;
    float* sBias = sm + 16384;
    float* sSum  = sm + 16512;
    float* sSsq  = sm + 16640;
    int blk = blockIdx.x, t = threadIdx.x;
    int w = t >> 5, lane = t & 31;
    sBias[t] = b0[t]; sSum[t] = 0.f; sSsq[t] = 0.f;

    int m = t;
    int c2 = blk*2 + (m >> 6);
    int e  = m & 63;
    int cnt_my = g_cnt[c2];
    bool val = e < cnt_my;
    int j = val ? g_nbr[c2*KNB + e] : 0;
    int bcl = c2 >> 11;
    const float* xrow = x + ((size_t)(bcl*NPTS + j))*CIN;
    float4 P = g_pos4[bcl*NPTS + j];
    float dx = P.x - g_ctr[c2*3], dy = P.y - g_ctr[c2*3+1], dz = P.z - g_ctr[c2*3+2];

    float acc[2][16][4];
#pragma unroll
    for (int a = 0; a < 2; a++)
#pragma unroll
        for (int b = 0; b < 16; b++)
#pragma unroll
            for (int r = 0; r < 4; r++) acc[a][b][r] = 0.f;

#pragma unroll 1
    for (int s = 0; s < 3; s++) {
        __syncthreads();
        {
            const float4* src = (const float4*)(g_WF0 + s*8192);
            float4* dstp = (float4*)sBh;
            for (int i = t; i < 2048; i += 128) dstp[i] = src[i];
        }
        if (s < 2) {
#pragma unroll
            for (int q = 0; q < 8; q++) {
                float4 v4 = val ? *(const float4*)(xrow + s*32 + q*4)
                                : make_float4(0.f,0.f,0.f,0.f);
                putA(sAh, sAl, m, q*4+0, v4.x);
                putA(sAh, sAl, m, q*4+1, v4.y);
                putA(sAh, sAl, m, q*4+2, v4.z);
                putA(sAh, sAl, m, q*4+3, v4.w);
            }
        } else {
            putA(sAh, sAl, m, 0, val ? dx : 0.f);
            putA(sAh, sAl, m, 1, val ? dy : 0.f);
            putA(sAh, sAl, m, 2, val ? dz : 0.f);
#pragma unroll
            for (int q = 3; q < 8; q++) putA(sAh, sAl, m, q, 0.f);
        }
        __syncthreads();
        int nkk = (s < 2) ? 4 : 1;
#pragma unroll 1
        for (int pass = 0; pass < 3; pass++) {
            const float* pA = (pass == 2) ? sAl : sAh;
            const float* pB = (pass == 1) ? sBl : sBh;
#pragma unroll 1
            for (int kk = 0; kk < nkk; kk++) {
                float4 a0 = *(const float4*)&pA[((kk*8 + 2*w  )*32 + lane)*4];
                float4 a1 = *(const float4*)&pA[((kk*8 + 2*w+1)*32 + lane)*4];
#pragma unroll
                for (int tt = 0; tt < 16; tt++) {
                    float2 bfr = *(const float2*)&pB[((kk*16 + tt)*32 + lane)*2];
                    mma8(acc[0][tt], a0, bfr);
                    mma8(acc[1][tt], a1, bfr);
                }
            }
        }
    }
    int g = lane >> 2, tig = lane & 3;
    int cnt0 = g_cnt[blk*2], cnt1 = g_cnt[blk*2+1];
#pragma unroll
    for (int tt = 0; tt < 16; tt++) {
        int n0 = tt*8 + tig*2;
        float bz0 = sBias[n0], bz1 = sBias[n0+1];
        float s0 = 0.f, s1 = 0.f, q0 = 0.f, q1 = 0.f;
#pragma unroll
        for (int fl = 0; fl < 2; fl++)
#pragma unroll
            for (int rh = 0; rh < 2; rh++) {
                int mr = 32*w + 16*fl + 8*rh + g;
                float z0 = acc[fl][tt][rh*2+0] + bz0;
                float z1 = acc[fl][tt][rh*2+1] + bz1;
                *(float2*)(g_H0 + ((size_t)(blk*128 + mr))*HID + n0) = make_float2(z0, z1);
                int ee = mr & 63;
                int cc = (mr >> 6) ? cnt1 : cnt0;
                if (ee < cc) { s0 += z0; q0 = fmaf(z0,z0,q0); s1 += z1; q1 = fmaf(z1,z1,q1); }
            }
#pragma unroll
        for (int o = 4; o <= 16; o <<= 1) {
            s0 += __shfl_down_sync(0xffffffffu, s0, o);
            s1 += __shfl_down_sync(0xffffffffu, s1, o);
            q0 += __shfl_down_sync(0xffffffffu, q0, o);
            q1 += __shfl_down_sync(0xffffffffu, q1, o);
        }
        if (g == 0) {
            atomicAdd(&sSum[n0], s0); atomicAdd(&sSum[n0+1], s1);
            atomicAdd(&sSsq[n0], q0); atomicAdd(&sSsq[n0+1], q1);
        }
    }
    __syncthreads();
    atomicAdd(&g_stat[0][0][blk & 31][t], (double)sSum[t]);
    atomicAdd(&g_stat[0][1][blk & 31][t], (double)sSsq[t]);
}

// ---------------- bn prepare ----------------
__global__ void k_prep(const float* __restrict__ gamma,
                       const float* __restrict__ beta, int layer) {
    int t = threadIdx.x;
    int local = 0;
    for (int i = t; i < BSZ; i += 128) local += g_cnt[i];
    __shared__ int sred[4];
    int lane = t & 31, w = t >> 5;
#pragma unroll
    for (int off = 16; off > 0; off >>= 1)
        local += __shfl_down_sync(0xffffffffu, local, off);
    if (lane == 0) sred[w] = local;
    __syncthreads();
    double cntd = (double)(sred[0] + sred[1] + sred[2] + sred[3]);
    double s = 0.0, q = 0.0;
    for (int k = 0; k < 32; k++) {
        s += g_stat[layer][0][k][t];
        q += g_stat[layer][1][k][t];
    }
    double mean = s / cntd;
    double var = q / cntd - mean * mean;
    if (var < 0.0) var = 0.0;
    double a = (double)gamma[t] * rsqrt(var + 1e-5);
    g_scale[layer][t] = (float)a;
    g_shift[layer][t] = (float)((double)beta[t] - mean * a);
}

// ---------------- layer 1 GEMM: bnrelu0(H0) @ W1 + b1, stats ----------------
__global__ void __launch_bounds__(128) k_l1(const float* __restrict__ b1) {
    extern __shared__ float sm[];
    float* sAh   = sm;
    float* sAl   = sm + 4096;
    float* sBh   = sm + 8192;
    float* sBl   = sm + 12288;
    float* sSc   = sm + 16384;
    float* sSh   = sm + 16512;
    float* sBias = sm + 16640;
    float* sSum  = sm + 16768;
    float* sSsq  = sm + 16896;
    int blk = blockIdx.x, t = threadIdx.x;
    int w = t >> 5, lane = t & 31;
    sSc[t] = g_scale[0][t]; sSh[t] = g_shift[0][t];
    sBias[t] = b1[t]; sSum[t] = 0.f; sSsq[t] = 0.f;

    int m = t;
    const float* hrow = g_H0 + ((size_t)(blk*128 + m))*HID;

    float acc[2][16][4];
#pragma unroll
    for (int a = 0; a < 2; a++)
#pragma unroll
        for (int b = 0; b < 16; b++)
#pragma unroll
            for (int r = 0; r < 4; r++) acc[a][b][r] = 0.f;

#pragma unroll 1
    for (int s = 0; s < 4; s++) {
        __syncthreads();
        {
            const float4* src = (const float4*)(g_WF1 + s*8192);
            float4* dstp = (float4*)sBh;
            for (int i = t; i < 2048; i += 128) dstp[i] = src[i];
        }
#pragma unroll
        for (int q = 0; q < 8; q++) {
            float4 v4 = *(const float4*)(hrow + s*32 + q*4);
            int k0 = s*32 + q*4;
            putA(sAh, sAl, m, q*4+0, fmaxf(0.f, fmaf(v4.x, sSc[k0+0], sSh[k0+0])));
            putA(sAh, sAl, m, q*4+1, fmaxf(0.f, fmaf(v4.y, sSc[k0+1], sSh[k0+1])));
            putA(sAh, sAl, m, q*4+2, fmaxf(0.f, fmaf(v4.z, sSc[k0+2], sSh[k0+2])));
            putA(sAh, sAl, m, q*4+3, fmaxf(0.f, fmaf(v4.w, sSc[k0+3], sSh[k0+3])));
        }
        __syncthreads();
#pragma unroll 1
        for (int pass = 0; pass < 3; pass++) {
            const float* pA = (pass == 2) ? sAl : sAh;
            const float* pB = (pass == 1) ? sBl : sBh;
#pragma unroll 1
            for (int kk = 0; kk < 4; kk++) {
                float4 a0 = *(const float4*)&pA[((kk*8 + 2*w  )*32 + lane)*4];
                float4 a1 = *(const float4*)&pA[((kk*8 + 2*w+1)*32 + lane)*4];
#pragma unroll
                for (int tt = 0; tt < 16; tt++) {
                    float2 bfr = *(const float2*)&pB[((kk*16 + tt)*32 + lane)*2];
                    mma8(acc[0][tt], a0, bfr);
                    mma8(acc[1][tt], a1, bfr);
                }
            }
        }
    }
    int g = lane >> 2, tig = lane & 3;
    int cnt0 = g_cnt[blk*2], cnt1 = g_cnt[blk*2+1];
#pragma unroll
    for (int tt = 0; tt < 16; tt++) {
        int n0 = tt*8 + tig*2;
        float bz0 = sBias[n0], bz1 = sBias[n0+1];
        float s0 = 0.f, s1 = 0.f, q0 = 0.f, q1 = 0.f;
#pragma unroll
        for (int fl = 0; fl < 2; fl++)
#pragma unroll
            for (int rh = 0; rh < 2; rh++) {
                int mr = 32*w + 16*fl + 8*rh + g;
                float z0 = acc[fl][tt][rh*2+0] + bz0;
                float z1 = acc[fl][tt][rh*2+1] + bz1;
                *(float2*)(g_H1 + ((size_t)(blk*128 + mr))*HID + n0) = make_float2(z0, z1);
                int ee = mr & 63;
                int cc = (mr >> 6) ? cnt1 : cnt0;
                if (ee < cc) { s0 += z0; q0 = fmaf(z0,z0,q0); s1 += z1; q1 = fmaf(z1,z1,q1); }
            }
#pragma unroll
        for (int o = 4; o <= 16; o <<= 1) {
            s0 += __shfl_down_sync(0xffffffffu, s0, o);
            s1 += __shfl_down_sync(0xffffffffu, s1, o);
            q0 += __shfl_down_sync(0xffffffffu, q0, o);
            q1 += __shfl_down_sync(0xffffffffu, q1, o);
        }
        if (g == 0) {
            atomicAdd(&sSum[n0], s0); atomicAdd(&sSum[n0+1], s1);
            atomicAdd(&sSsq[n0], q0); atomicAdd(&sSsq[n0+1], q1);
        }
    }
    __syncthreads();
    atomicAdd(&g_stat[1][0][blk & 31][t], (double)sSum[t]);
    atomicAdd(&g_stat[1][1][blk & 31][t], (double)sSsq[t]);
}

// ---------------- layer 2 GEMM: bnrelu1(H1) @ W2 + b2, masked max ----------------
__global__ void __launch_bounds__(128) k_l2(const float* __restrict__ b2,
                                            float* __restrict__ outp) {
    extern __shared__ float sm[];
    float* sAh   = sm;
    float* sAl   = sm + 4096;
    float* sBh   = sm + 8192;
    float* sBl   = sm + 12288;
    float* sSc   = sm + 16384;
    float* sSh   = sm + 16512;
    float* sBias = sm + 16640;
    float* sMax  = sm + 16768;     // 4 warps * 128
    int blk = blockIdx.x, t = threadIdx.x;
    int w = t >> 5, lane = t & 31;
    sSc[t] = g_scale[1][t]; sSh[t] = g_shift[1][t];
    sBias[t] = b2[t];

    int m = t;
    const float* hrow = g_H1 + ((size_t)(blk*128 + m))*HID;

    float acc[2][16][4];
#pragma unroll
    for (int a = 0; a < 2; a++)
#pragma unroll
        for (int b = 0; b < 16; b++)
#pragma unroll
            for (int r = 0; r < 4; r++) acc[a][b][r] = 0.f;

#pragma unroll 1
    for (int s = 0; s < 4; s++) {
        __syncthreads();
        {
            const float4* src = (const float4*)(g_WF2 + s*8192);
            float4* dstp = (float4*)sBh;
            for (int i = t; i < 2048; i += 128) dstp[i] = src[i];
        }
#pragma unroll
        for (int q = 0; q < 8; q++) {
            float4 v4 = *(const float4*)(hrow + s*32 + q*4);
            int k0 = s*32 + q*4;
            putA(sAh, sAl, m, q*4+0, fmaxf(0.f, fmaf(v4.x, sSc[k0+0], sSh[k0+0])));
            putA(sAh, sAl, m, q*4+1, fmaxf(0.f, fmaf(v4.y, sSc[k0+1], sSh[k0+1])));
            putA(sAh, sAl, m, q*4+2, fmaxf(0.f, fmaf(v4.z, sSc[k0+2], sSh[k0+2])));
            putA(sAh, sAl, m, q*4+3, fmaxf(0.f, fmaf(v4.w, sSc[k0+3], sSh[k0+3])));
        }
        __syncthreads();
#pragma unroll 1
        for (int pass = 0; pass < 3; pass++) {
            const float* pA = (pass == 2) ? sAl : sAh;
            const float* pB = (pass == 1) ? sBl : sBh;
#pragma unroll 1
            for (int kk = 0; kk < 4; kk++) {
                float4 a0 = *(const float4*)&pA[((kk*8 + 2*w  )*32 + lane)*4];
                float4 a1 = *(const float4*)&pA[((kk*8 + 2*w+1)*32 + lane)*4];
#pragma unroll
                for (int tt = 0; tt < 16; tt++) {
                    float2 bfr = *(const float2*)&pB[((kk*16 + tt)*32 + lane)*2];
                    mma8(acc[0][tt], a0, bfr);
                    mma8(acc[1][tt], a1, bfr);
                }
            }
        }
    }
    int g = lane >> 2, tig = lane & 3;
    int cnt0 = g_cnt[blk*2], cnt1 = g_cnt[blk*2+1];
    const float NINF = __int_as_float(0xff800000);
#pragma unroll
    for (int tt = 0; tt < 16; tt++) {
        int n0 = tt*8 + tig*2;
        float bz0 = sBias[n0], bz1 = sBias[n0+1];
        float m0 = NINF, m1 = NINF;
#pragma unroll
        for (int fl = 0; fl < 2; fl++)
#pragma unroll
            for (int rh = 0; rh < 2; rh++) {
                int mr = 32*w + 16*fl + 8*rh + g;
                int ee = mr & 63;
                int cc = (mr >> 6) ? cnt1 : cnt0;
                if (ee < cc) {
                    m0 = fmaxf(m0, acc[fl][tt][rh*2+0] + bz0);
                    m1 = fmaxf(m1, acc[fl][tt][rh*2+1] + bz1);
                }
            }
#pragma unroll
        for (int o = 4; o <= 16; o <<= 1) {
            m0 = fmaxf(m0, __shfl_down_sync(0xffffffffu, m0, o));
            m1 = fmaxf(m1, __shfl_down_sync(0xffffffffu, m1, o));
        }
        if (g == 0) { sMax[w*128 + n0] = m0; sMax[w*128 + n0 + 1] = m1; }
    }
    __syncthreads();
    int ci = t >> 6;
#pragma unroll
    for (int rep = 0; rep < 2; rep++) {
        int col = (t & 63) + rep*64;
        float v = fmaxf(sMax[(2*ci)*128 + col], sMax[(2*ci+1)*128 + col]);
        outp[((size_t)(blk*2 + ci))*HID + col] = v;
    }
}

// ---------------- launch ----------------
extern "C" void kernel_launch(void* const* d_in, const int* in_sizes, int n_in,
                              void* d_out, int out_size) {
    const float* x   = (const float*)d_in[0];
    const float* pos = (const float*)d_in[1];
    const float* W0  = (const float*)d_in[3];
    const float* b0  = (const float*)d_in[4];
    const float* g0  = (const float*)d_in[5];
    const float* be0 = (const float*)d_in[6];
    const float* W1  = (const float*)d_in[7];
    const float* b1  = (const float*)d_in[8];
    const float* g1  = (const float*)d_in[9];
    const float* be1 = (const float*)d_in[10];
    const float* W2  = (const float*)d_in[11];
    const float* b2  = (const float*)d_in[12];
    float* out = (float*)d_out;

    float* octr = (out_size >= BSZ*HID + BSZ*3) ? out + (size_t)BSZ*HID : nullptr;
    float* obat = (out_size >= BSZ*HID + BSZ*3 + BSZ) ? out + (size_t)BSZ*131 : nullptr;

    int sm0 = (16384 + 384) * 4;
    int sm1 = (16384 + 640) * 4;
    int sm2 = (16384 + 384 + 512) * 4;
    cudaFuncSetAttribute(k_l0, cudaFuncAttributeMaxDynamicSharedMemorySize, sm0);
    cudaFuncSetAttribute(k_l1, cudaFuncAttributeMaxDynamicSharedMemorySize, sm1);
    cudaFuncSetAttribute(k_l2, cudaFuncAttributeMaxDynamicSharedMemorySize, sm2);

    k_zero<<<32, 256>>>();
    k_pos4<<<(BB*NPTS + 255)/256, 256>>>(pos);
    k_wprep<<<(3*4096 + 255)/256, 256>>>(W0, 67, 3, 0);
    k_wprep<<<(4*4096 + 255)/256, 256>>>(W1, HID, 4, 1);
    k_wprep<<<(4*4096 + 255)/256, 256>>>(W2, HID, 4, 2);
    k_fps<<<BB, 1024>>>(pos, octr, obat);
    k_nbr<<<BSZ, 128>>>();
    k_l0<<<NBLK, 128, sm0>>>(x, b0);
    k_prep<<<1, 128>>>(g0, be0, 0);
    k_l1<<<NBLK, 128, sm1>>>(b1);
    k_prep<<<1, 128>>>(g1, be1, 1);
    k_l2<<<NBLK, 128, sm2>>>(b2, out);
}

// round 9
// speedup vs baseline: 2.2956x; 2.2956x over previous
#include <cuda_runtime.h>
#include <cstdint>
#include <cstddef>

#define BB   8
#define NPTS 4096
#define SS   2048
#define KNB  64
#define CIN  64
#define HID  128
#define BSZ  (BB*SS)
#define R2F  0.04f
#define MAXC 1024
#define NBLK (BSZ/2)          // 2 centroids per GEMM block
#define SROW 132              // fp32 staging row stride

// ---------------- device scratch ----------------
__device__ float  g_ctr[BSZ*3];
__device__ int    g_nbr[BSZ*KNB];
__device__ int    g_cnt[BSZ];
__device__ float4 g_pos4[BB*NPTS];
__device__ float  g_H0[(size_t)NBLK*128*HID];
__device__ float  g_H1[(size_t)NBLK*128*HID];
__device__ double g_stat[2][2][32][HID];
__device__ float  g_scale[2][HID];
__device__ float  g_shift[2][HID];
// fragment-ordered tf32 hi/lo weights: per slab 8192 floats = [hi 4096 | lo 4096]
__device__ float  g_WF0[3*8192];
__device__ float  g_WF1[4*8192];
__device__ float  g_WF2[4*8192];

// ---------------- helpers ----------------
__device__ __forceinline__ float tf32hi(float v) {
    unsigned u;
    asm("cvt.rna.tf32.f32 %0, %1;" : "=r"(u) : "f"(v));
    return __uint_as_float(u);
}

__device__ __forceinline__ void mma8(float* c, float a0, float a1, float a2, float a3,
                                     float b0, float b1) {
    asm volatile("mma.sync.aligned.m16n8k8.row.col.f32.tf32.tf32.f32 "
        "{%0,%1,%2,%3}, {%4,%5,%6,%7}, {%8,%9}, {%0,%1,%2,%3};\n"
        : "+f"(c[0]), "+f"(c[1]), "+f"(c[2]), "+f"(c[3])
        : "r"(__float_as_uint(a0)), "r"(__float_as_uint(a1)),
          "r"(__float_as_uint(a2)), "r"(__float_as_uint(a3)),
          "r"(__float_as_uint(b0)), "r"(__float_as_uint(b1)));
}

// main GEMM slab: A from row-major fp32 staging (split in regs), B pre-split frag images
__device__ __forceinline__ void gemm_slab(const float* sA, const float* sB,
                                          float (*acc)[4], int w, int lane, int scol) {
    int g = lane >> 2, tig = lane & 3;
    const float* bh = sB;
    const float* bl = sB + 4096;
#pragma unroll 1
    for (int kk = 0; kk < 4; kk++) {
        const float* base = sA + (32*w + g)*SROW + scol + kk*8 + tig;
        float v0 = base[0],         v1 = base[8*SROW],       v2 = base[4],          v3 = base[8*SROW+4];
        float v4 = base[16*SROW],   v5 = base[24*SROW],      v6 = base[16*SROW+4],  v7 = base[24*SROW+4];
        float h0 = tf32hi(v0), h1 = tf32hi(v1), h2 = tf32hi(v2), h3 = tf32hi(v3);
        float h4 = tf32hi(v4), h5 = tf32hi(v5), h6 = tf32hi(v6), h7 = tf32hi(v7);
        float l0 = tf32hi(v0-h0), l1 = tf32hi(v1-h1), l2 = tf32hi(v2-h2), l3 = tf32hi(v3-h3);
        float l4 = tf32hi(v4-h4), l5 = tf32hi(v5-h5), l6 = tf32hi(v6-h6), l7 = tf32hi(v7-h7);
        const float* bbh = bh + kk*1024;
        const float* bbl = bl + kk*1024;
#pragma unroll
        for (int tt = 0; tt < 16; tt++) {
            float2 b2 = *(const float2*)&bbh[(tt*32+lane)*2];
            mma8(acc[tt],    h0,h1,h2,h3, b2.x,b2.y);
            mma8(acc[16+tt], h4,h5,h6,h7, b2.x,b2.y);
        }
#pragma unroll
        for (int tt = 0; tt < 16; tt++) {
            float2 b2 = *(const float2*)&bbh[(tt*32+lane)*2];
            mma8(acc[tt],    l0,l1,l2,l3, b2.x,b2.y);
            mma8(acc[16+tt], l4,l5,l6,l7, b2.x,b2.y);
        }
#pragma unroll
        for (int tt = 0; tt < 16; tt++) {
            float2 b2 = *(const float2*)&bbl[(tt*32+lane)*2];
            mma8(acc[tt],    h0,h1,h2,h3, b2.x,b2.y);
            mma8(acc[16+tt], h4,h5,h6,h7, b2.x,b2.y);
        }
    }
}

// acc -> (+bias) -> staging rows (warp writes only its own rows; no sync needed)
__device__ __forceinline__ void epi_to_stage(float* sA, float (*acc)[4], const float* bias,
                                             int w, int lane) {
    int g = lane >> 2, tig = lane & 3;
#pragma unroll
    for (int rt = 0; rt < 2; rt++)
#pragma unroll
        for (int tt = 0; tt < 16; tt++) {
            int n0 = tt*8 + tig*2;
            float bz0 = bias[n0], bz1 = bias[n0+1];
            float* r0 = sA + (32*w + 16*rt + g)*SROW + n0;
            const float* a = acc[rt*16 + tt];
            *(float2*)r0            = make_float2(a[0]+bz0, a[1]+bz1);
            *(float2*)(r0 + 8*SROW) = make_float2(a[2]+bz0, a[3]+bz1);
        }
}

// ---------------- zero stats ----------------
__global__ void k_zero() {
    int i = blockIdx.x * blockDim.x + threadIdx.x;
    const int n = 2*2*32*HID;
    double* p = &g_stat[0][0][0][0];
    for (; i < n; i += gridDim.x * blockDim.x) p[i] = 0.0;
}

// ---------------- pos -> float4 ----------------
__global__ void k_pos4(const float* __restrict__ pos) {
    int i = blockIdx.x * blockDim.x + threadIdx.x;
    if (i < BB*NPTS)
        g_pos4[i] = make_float4(pos[3*i], pos[3*i+1], pos[3*i+2], 0.f);
}

// ---------------- weight fragment prep (tf32 hi/lo) — verified layout (R7 passed) ----------------
__global__ void k_wprep(const float* __restrict__ W, int K, int nslab, int which) {
    float* dst = (which == 0) ? g_WF0 : (which == 1) ? g_WF1 : g_WF2;
    int i = blockIdx.x * blockDim.x + threadIdx.x;
    int tot = nslab * 4096;
    if (i >= tot) return;
    int s = i >> 12, r = i & 4095;
    int reg = r & 1, lane = (r >> 1) & 31, tt = (r >> 6) & 15, kk = (r >> 10) & 3;
    int k = s*32 + kk*8 + reg*4 + (lane & 3);
    int n = tt*8 + (lane >> 2);
    float v = (k < K) ? W[k*HID + n] : 0.f;
    float h = tf32hi(v);
    dst[s*8192 + r]        = h;
    dst[s*8192 + 4096 + r] = tf32hi(v - h);
}

// ---------------- farthest point sampling (redux.sync reduction) ----------------
__global__ void __launch_bounds__(1024) k_fps(const float* __restrict__ pos,
                                              float* __restrict__ octr,
                                              float* __restrict__ obat) {
    int b = blockIdx.x, t = threadIdx.x;
    const float* p = pos + (size_t)b * NPTS * 3;
    float px[4], py[4], pz[4], md[4];
#pragma unroll
    for (int j = 0; j < 4; j++) {
        int i = t + j * 1024;
        px[j] = p[3*i]; py[j] = p[3*i+1]; pz[j] = p[3*i+2];
        md[j] = __int_as_float(0x7f800000);
    }
    __shared__ unsigned svk[32];
    __shared__ unsigned svi[32];
    __shared__ int sLast;
    int lane = t & 31, w = t >> 5;
    int last = 0;
    for (int s = 0; s < SS; s++) {
        float qx = p[3*last], qy = p[3*last+1], qz = p[3*last+2];
        if (t == 0) {
            int o = b*SS + s;
            g_ctr[o*3] = qx; g_ctr[o*3+1] = qy; g_ctr[o*3+2] = qz;
            if (octr) { octr[o*3] = qx; octr[o*3+1] = qy; octr[o*3+2] = qz; }
            if (obat) obat[o] = (float)b;
        }
        float bv = -1.f; int bi = 0;
#pragma unroll
        for (int j = 0; j < 4; j++) {
            float dx = px[j]-qx, dy = py[j]-qy, dz = pz[j]-qz;
            float d = fmaf(dz, dz, fmaf(dy, dy, __fmul_rn(dx, dx)));
            md[j] = fminf(md[j], d);
            if (md[j] > bv) { bv = md[j]; bi = t + j*1024; }  // strict >: lowest idx wins
        }
        // bv >= 0 always, so fp bits are order-isomorphic to unsigned
        unsigned key  = __float_as_uint(bv);
        unsigned vmax = __reduce_max_sync(0xffffffffu, key);
        unsigned cand = (key == vmax) ? (unsigned)bi : 0xffffffffu;
        unsigned imin = __reduce_min_sync(0xffffffffu, cand);
        if (lane == 0) { svk[w] = vmax; svi[w] = imin; }
        __syncthreads();
        if (w == 0) {
            unsigned k2 = svk[lane], i2 = svi[lane];
            unsigned vm2 = __reduce_max_sync(0xffffffffu, k2);
            unsigned c2  = (k2 == vm2) ? i2 : 0xffffffffu;
            unsigned im2 = __reduce_min_sync(0xffffffffu, c2);
            if (lane == 0) sLast = (int)im2;
        }
        __syncthreads();
        last = sLast;
    }
}

// ---------------- radius-capped kNN (known-good) ----------------
__global__ void __launch_bounds__(128) k_nbr() {
    int c = blockIdx.x, t = threadIdx.x;
    int b = c >> 11;
    __shared__ float sd[MAXC];
    __shared__ int   sid[MAXC];
    __shared__ int   hist[128];
    __shared__ int   sc, so, s_tb, s_m, tc;
    __shared__ float td[256];
    __shared__ int   tdi[256];
    __shared__ int   wtot[4];
    if (t == 0) { sc = 0; so = 0; tc = 0; }
    hist[t] = 0;
    float cx = g_ctr[c*3], cy = g_ctr[c*3+1], cz = g_ctr[c*3+2];
    __syncthreads();
    for (int i = t; i < NPTS; i += 128) {
        float4 P = g_pos4[b*NPTS + i];
        float dx = P.x-cx, dy = P.y-cy, dz = P.z-cz;
        float d = fmaf(dz, dz, fmaf(dy, dy, __fmul_rn(dx, dx)));
        if (d <= R2F) {
            int k = atomicAdd(&sc, 1);
            if (k < MAXC) { sd[k] = d; sid[k] = i; }
        }
    }
    __syncthreads();
    int cnt = min(sc, MAXC);
    if (cnt <= KNB) {
        if (t < cnt) g_nbr[c*KNB + t] = sid[t];
        if (t == 0) g_cnt[c] = cnt;
        return;
    }
    const float bsc = 128.0f / R2F;
    for (int i = t; i < cnt; i += 128) {
        int bk = min(127, (int)(sd[i] * bsc));
        atomicAdd(&hist[bk], 1);
    }
    __syncthreads();
    {
        int lane = t & 31, w = t >> 5;
        int h = hist[t], v = h;
#pragma unroll
        for (int o = 1; o < 32; o <<= 1) {
            int u = __shfl_up_sync(0xffffffffu, v, o);
            if (lane >= o) v += u;
        }
        if (lane == 31) wtot[w] = v;
        __syncthreads();
        int base = 0;
        for (int k2 = 0; k2 < w; k2++) base += wtot[k2];
        int incl = v + base, excl = incl - h;
        if (incl >= KNB && excl < KNB) { s_tb = t; s_m = excl; }
    }
    __syncthreads();
    int tb = s_tb, m = s_m;
    for (int i = t; i < cnt; i += 128) {
        int bk = min(127, (int)(sd[i] * bsc));
        if (bk < tb) {
            int k = atomicAdd(&so, 1);
            g_nbr[c*KNB + k] = sid[i];
        } else if (bk == tb) {
            int k = atomicAdd(&tc, 1);
            if (k < 256) { td[k] = sd[i]; tdi[k] = sid[i]; }
        }
    }
    __syncthreads();
    int bn = min(tc, 256), rem = KNB - m;
    for (int i = t; i < bn; i += 128) {
        float di = td[i]; int ii = tdi[i];
        int rank = 0;
        for (int j2 = 0; j2 < bn; j2++) {
            float dj = td[j2]; int ij = tdi[j2];
            if (dj < di || (dj == di && ij < ii)) rank++;
        }
        if (rank < rem) {
            int k = atomicAdd(&so, 1);
            g_nbr[c*KNB + k] = tdi[i];
        }
    }
    if (t == 0) g_cnt[c] = KNB;
}

// ---------------- layer 0: gather -> GEMM(K slabs 0..2) -> H0 + stats ----------------
__global__ void __launch_bounds__(128, 2) k_l0(const float* __restrict__ x,
                                               const float* __restrict__ b0) {
    extern __shared__ float sm[];
    float* sA   = sm;                  // 128*132
    float* sB   = sm + 128*SROW;       // 8192
    float* bias = sB + 8192;           // 128
    int t = threadIdx.x, w = t >> 5, lane = t & 31, blk = blockIdx.x;
    bias[t] = b0[t];

    // zero A staging (cols >=67 and invalid rows MUST be 0 to avoid NaN*0)
    {
        float4 z = make_float4(0.f, 0.f, 0.f, 0.f);
        for (int i = t; i < 128*33; i += 128)
            *(float4*)(sA + (i/33)*SROW + (i%33)*4) = z;
    }
    __syncthreads();

    // gather: row t = edge
    int c2 = blk*2 + (t >> 6), e = t & 63;
    int cnt_my = g_cnt[c2];
    if (e < cnt_my) {
        int j = g_nbr[c2*KNB + e];
        int bcl = c2 >> 11;
        const float4* xr = (const float4*)(x + (size_t)(bcl*NPTS + j)*CIN);
        float* row = sA + t*SROW;
#pragma unroll
        for (int q = 0; q < 16; q++)
            *(float4*)(row + 4*q) = xr[q];
        float4 P = g_pos4[bcl*NPTS + j];
        row[64] = P.x - g_ctr[c2*3];
        row[65] = P.y - g_ctr[c2*3+1];
        row[66] = P.z - g_ctr[c2*3+2];
    }

    float acc[32][4];
#pragma unroll
    for (int i = 0; i < 32; i++)
#pragma unroll
        for (int r = 0; r < 4; r++) acc[i][r] = 0.f;

#pragma unroll 1
    for (int s = 0; s < 3; s++) {
        __syncthreads();
        const float4* src = (const float4*)(g_WF0 + s*8192);
        float4* dst = (float4*)sB;
        for (int i = t; i < 2048; i += 128) dst[i] = src[i];
        __syncthreads();
        gemm_slab(sA, sB, acc, w, lane, s*32);
    }

    epi_to_stage(sA, acc, bias, w, lane);
    __syncthreads();

    // coalesced H0 write
    float4* dstH = (float4*)(g_H0 + (size_t)blk * 16384);
    for (int i = t; i < 4096; i += 128)
        dstH[i] = *(const float4*)(sA + (i >> 5)*SROW + (i & 31)*4);

    // column-wise masked stats (conflict-free: bank = 4r+t distinct per row)
    int cnt0 = g_cnt[blk*2], cnt1 = g_cnt[blk*2+1];
    float ssum = 0.f, ssq = 0.f;
    for (int r = 0; r < 128; r++) {
        bool val = (r & 63) < ((r >> 6) ? cnt1 : cnt0);
        float v = sA[r*SROW + t];
        if (val) { ssum += v; ssq = fmaf(v, v, ssq); }
    }
    atomicAdd(&g_stat[0][0][blk & 31][t], (double)ssum);
    atomicAdd(&g_stat[0][1][blk & 31][t], (double)ssq);
}

// ---------------- bn prepare ----------------
__global__ void k_prep(const float* __restrict__ gamma,
                       const float* __restrict__ beta, int layer) {
    int t = threadIdx.x;
    int local = 0;
    for (int i = t; i < BSZ; i += 128) local += g_cnt[i];
    __shared__ int sred[4];
    int lane = t & 31, w = t >> 5;
#pragma unroll
    for (int off = 16; off > 0; off >>= 1)
        local += __shfl_down_sync(0xffffffffu, local, off);
    if (lane == 0) sred[w] = local;
    __syncthreads();
    double cntd = (double)(sred[0] + sred[1] + sred[2] + sred[3]);
    double s = 0.0, q = 0.0;
    for (int k = 0; k < 32; k++) {
        s += g_stat[layer][0][k][t];
        q += g_stat[layer][1][k][t];
    }
    double mean = s / cntd;
    double var = q / cntd - mean * mean;
    if (var < 0.0) var = 0.0;
    double a = (double)gamma[t] * rsqrt(var + 1e-5);
    g_scale[layer][t] = (float)a;
    g_shift[layer][t] = (float)((double)beta[t] - mean * a);
}

// ---------------- layer 1: bnrelu(H0) -> GEMM -> H1 + stats ----------------
__global__ void __launch_bounds__(128, 2) k_l1(const float* __restrict__ b1) {
    extern __shared__ float sm[];
    float* sA   = sm;
    float* sB   = sm + 128*SROW;
    float* bias = sB + 8192;
    float* sc   = bias + 128;
    float* sh   = sc + 128;
    int t = threadIdx.x, w = t >> 5, lane = t & 31, blk = blockIdx.x;
    bias[t] = b1[t]; sc[t] = g_scale[0][t]; sh[t] = g_shift[0][t];
    __syncthreads();

    // stage bnrelu(H0) coalesced
    const float4* src = (const float4*)(g_H0 + (size_t)blk * 16384);
    for (int i = t; i < 4096; i += 128) {
        int row = i >> 5, c4 = (i & 31) * 4;
        float4 v = src[i];
        float4 z;
        z.x = fmaxf(0.f, fmaf(v.x, sc[c4+0], sh[c4+0]));
        z.y = fmaxf(0.f, fmaf(v.y, sc[c4+1], sh[c4+1]));
        z.z = fmaxf(0.f, fmaf(v.z, sc[c4+2], sh[c4+2]));
        z.w = fmaxf(0.f, fmaf(v.w, sc[c4+3], sh[c4+3]));
        *(float4*)(sA + row*SROW + c4) = z;
    }

    float acc[32][4];
#pragma unroll
    for (int i = 0; i < 32; i++)
#pragma unroll
        for (int r = 0; r < 4; r++) acc[i][r] = 0.f;

#pragma unroll 1
    for (int s = 0; s < 4; s++) {
        __syncthreads();
        const float4* wsrc = (const float4*)(g_WF1 + s*8192);
        float4* dst = (float4*)sB;
        for (int i = t; i < 2048; i += 128) dst[i] = wsrc[i];
        __syncthreads();
        gemm_slab(sA, sB, acc, w, lane, s*32);
    }

    epi_to_stage(sA, acc, bias, w, lane);
    __syncthreads();

    float4* dstH = (float4*)(g_H1 + (size_t)blk * 16384);
    for (int i = t; i < 4096; i += 128)
        dstH[i] = *(const float4*)(sA + (i >> 5)*SROW + (i & 31)*4);

    int cnt0 = g_cnt[blk*2], cnt1 = g_cnt[blk*2+1];
    float ssum = 0.f, ssq = 0.f;
    for (int r = 0; r < 128; r++) {
        bool val = (r & 63) < ((r >> 6) ? cnt1 : cnt0);
        float v = sA[r*SROW + t];
        if (val) { ssum += v; ssq = fmaf(v, v, ssq); }
    }
    atomicAdd(&g_stat[1][0][blk & 31][t], (double)ssum);
    atomicAdd(&g_stat[1][1][blk & 31][t], (double)ssq);
}

// ---------------- layer 2: bnrelu(H1) -> GEMM -> masked max -> out ----------------
__global__ void __launch_bounds__(128, 2) k_l2(const float* __restrict__ b2,
                                               float* __restrict__ outp) {
    extern __shared__ float sm[];
    float* sA   = sm;
    float* sB   = sm + 128*SROW;
    float* bias = sB + 8192;
    float* sc   = bias + 128;
    float* sh   = sc + 128;
    int t = threadIdx.x, w = t >> 5, lane = t & 31, blk = blockIdx.x;
    bias[t] = b2[t]; sc[t] = g_scale[1][t]; sh[t] = g_shift[1][t];
    __syncthreads();

    const float4* src = (const float4*)(g_H1 + (size_t)blk * 16384);
    for (int i = t; i < 4096; i += 128) {
        int row = i >> 5, c4 = (i & 31) * 4;
        float4 v = src[i];
        float4 z;
        z.x = fmaxf(0.f, fmaf(v.x, sc[c4+0], sh[c4+0]));
        z.y = fmaxf(0.f, fmaf(v.y, sc[c4+1], sh[c4+1]));
        z.z = fmaxf(0.f, fmaf(v.z, sc[c4+2], sh[c4+2]));
        z.w = fmaxf(0.f, fmaf(v.w, sc[c4+3], sh[c4+3]));
        *(float4*)(sA + row*SROW + c4) = z;
    }

    float acc[32][4];
#pragma unroll
    for (int i = 0; i < 32; i++)
#pragma unroll
        for (int r = 0; r < 4; r++) acc[i][r] = 0.f;

#pragma unroll 1
    for (int s = 0; s < 4; s++) {
        __syncthreads();
        const float4* wsrc = (const float4*)(g_WF2 + s*8192);
        float4* dst = (float4*)sB;
        for (int i = t; i < 2048; i += 128) dst[i] = wsrc[i];
        __syncthreads();
        gemm_slab(sA, sB, acc, w, lane, s*32);
    }

    epi_to_stage(sA, acc, bias, w, lane);
    __syncthreads();

    // masked max per column t, per centroid (conflict-free column reads)
    int cnt0 = g_cnt[blk*2], cnt1 = g_cnt[blk*2+1];
    const float NINF = __int_as_float(0xff800000);
    float m0 = NINF, m1 = NINF;
    for (int r = 0; r < 64; r++)
        if (r < cnt0) m0 = fmaxf(m0, sA[r*SROW + t]);
    for (int r = 64; r < 128; r++)
        if ((r - 64) < cnt1) m1 = fmaxf(m1, sA[r*SROW + t]);
    outp[(size_t)(blk*2)     * HID + t] = m0;
    outp[(size_t)(blk*2 + 1) * HID + t] = m1;
}

// ---------------- launch ----------------
extern "C" void kernel_launch(void* const* d_in, const int* in_sizes, int n_in,
                              void* d_out, int out_size) {
    const float* x   = (const float*)d_in[0];
    const float* pos = (const float*)d_in[1];
    const float* W0  = (const float*)d_in[3];
    const float* b0  = (const float*)d_in[4];
    const float* g0  = (const float*)d_in[5];
    const float* be0 = (const float*)d_in[6];
    const float* W1  = (const float*)d_in[7];
    const float* b1  = (const float*)d_in[8];
    const float* g1  = (const float*)d_in[9];
    const float* be1 = (const float*)d_in[10];
    const float* W2  = (const float*)d_in[11];
    const float* b2  = (const float*)d_in[12];
    float* out = (float*)d_out;

    float* octr = (out_size >= BSZ*HID + BSZ*3) ? out + (size_t)BSZ*HID : nullptr;
    float* obat = (out_size >= BSZ*HID + BSZ*3 + BSZ) ? out + (size_t)BSZ*131 : nullptr;

    int smB = (128*SROW + 8192 + 384) * 4;   // 101,888 B
    cudaFuncSetAttribute(k_l0, cudaFuncAttributeMaxDynamicSharedMemorySize, smB);
    cudaFuncSetAttribute(k_l1, cudaFuncAttributeMaxDynamicSharedMemorySize, smB);
    cudaFuncSetAttribute(k_l2, cudaFuncAttributeMaxDynamicSharedMemorySize, smB);

    k_zero<<<32, 256>>>();
    k_pos4<<<(BB*NPTS + 255)/256, 256>>>(pos);
    k_wprep<<<(3*4096 + 255)/256, 256>>>(W0, 67, 3, 0);
    k_wprep<<<(4*4096 + 255)/256, 256>>>(W1, HID, 4, 1);
    k_wprep<<<(4*4096 + 255)/256, 256>>>(W2, HID, 4, 2);
    k_fps<<<BB, 1024>>>(pos, octr, obat);
    k_nbr<<<BSZ, 128>>>();
    k_l0<<<NBLK, 128, smB>>>(x, b0);
    k_prep<<<1, 128>>>(g0, be0, 0);
    k_l1<<<NBLK, 128, smB>>>(b1);
    k_prep<<<1, 128>>>(g1, be1, 1);
    k_l2<<<NBLK, 128, smB>>>(b2, out);
}

// round 10
// speedup vs baseline: 2.7197x; 1.1848x over previous
#include <cuda_runtime.h>
#include <cuda_bf16.h>
#include <cstdint>
#include <cstddef>

#define BB   8
#define NPTS 4096
#define SS   2048
#define KNB  64
#define CIN  64
#define HID  128
#define BSZ  (BB*SS)
#define R2F  0.04f
#define MAXC 1024
#define NBLK (BSZ/2)          // 2 centroids per GEMM block
#define SROW 132              // fp32 staging row stride

// ---------------- device scratch ----------------
__device__ float  g_ctr[BSZ*3];
__device__ int    g_nbr[BSZ*KNB];
__device__ int    g_cnt[BSZ];
__device__ float4 g_pos4[BB*NPTS];
__device__ float  g_H0[(size_t)NBLK*128*HID];
__device__ float  g_H1[(size_t)NBLK*128*HID];
__device__ double g_stat[2][2][32][HID];
__device__ float  g_scale[2][HID];
__device__ float  g_shift[2][HID];
// fragment-ordered bf16 hi/lo weights: per slab 4096 u32 = [hi 2048 | lo 2048]
__device__ uint32_t g_WF0[3*4096];
__device__ uint32_t g_WF1[4*4096];
__device__ uint32_t g_WF2[4*4096];

// ---------------- helpers ----------------
__device__ __forceinline__ void split2(float x, float y, uint32_t& h, uint32_t& l) {
    __nv_bfloat162 hb = __floats2bfloat162_rn(x, y);
    h = *(uint32_t*)&hb;
    float lx = x - __bfloat162float(hb.x);
    float ly = y - __bfloat162float(hb.y);
    __nv_bfloat162 lb = __floats2bfloat162_rn(lx, ly);
    l = *(uint32_t*)&lb;
}

__device__ __forceinline__ void mma16(float* c, uint32_t a0, uint32_t a1, uint32_t a2,
                                      uint32_t a3, uint32_t b0, uint32_t b1) {
    asm volatile("mma.sync.aligned.m16n8k16.row.col.f32.bf16.bf16.f32 "
        "{%0,%1,%2,%3}, {%4,%5,%6,%7}, {%8,%9}, {%0,%1,%2,%3};\n"
        : "+f"(c[0]), "+f"(c[1]), "+f"(c[2]), "+f"(c[3])
        : "r"(a0), "r"(a1), "r"(a2), "r"(a3), "r"(b0), "r"(b1));
}

// GEMM slab: A from row-major fp32 staging (bf16 hi/lo split in regs),
// B from pre-split fragment images. nkk = number of K=16 chunks with nonzero A.
__device__ __forceinline__ void gemm_slab(const float* sA, const uint32_t* sB,
                                          float (*acc)[4], int w, int lane, int scol,
                                          int nkk) {
    int g = lane >> 2, tig = lane & 3;
    const uint32_t* bh = sB;
    const uint32_t* bl = sB + 2048;
#pragma unroll 1
    for (int kk = 0; kk < nkk; kk++) {
        uint32_t ah[2][4], al[2][4];
#pragma unroll
        for (int rt = 0; rt < 2; rt++) {
            const float* base = sA + (32*w + 16*rt + g)*SROW + scol + kk*16 + 2*tig;
            float2 v00 = *(const float2*)(base);            // (g,      2tig..)
            float2 v01 = *(const float2*)(base + 8);        // (g,      2tig+8..)
            float2 v10 = *(const float2*)(base + 8*SROW);   // (g+8,    2tig..)
            float2 v11 = *(const float2*)(base + 8*SROW+8); // (g+8,    2tig+8..)
            split2(v00.x, v00.y, ah[rt][0], al[rt][0]);
            split2(v10.x, v10.y, ah[rt][1], al[rt][1]);
            split2(v01.x, v01.y, ah[rt][2], al[rt][2]);
            split2(v11.x, v11.y, ah[rt][3], al[rt][3]);
        }
#pragma unroll
        for (int pass = 0; pass < 3; pass++) {
            const uint32_t (*pa)[4] = (pass == 1) ? al : ah;
            const uint32_t* pb = (pass == 2) ? bl : bh;
#pragma unroll
            for (int tt = 0; tt < 16; tt++) {
                uint2 b = *(const uint2*)&pb[((kk*16 + tt)*32 + lane)*2];
                mma16(acc[tt],    pa[0][0], pa[0][1], pa[0][2], pa[0][3], b.x, b.y);
                mma16(acc[16+tt], pa[1][0], pa[1][1], pa[1][2], pa[1][3], b.x, b.y);
            }
        }
    }
}

// acc -> (+bias) -> staging rows (warp writes only its own rows)
__device__ __forceinline__ void epi_to_stage(float* sA, float (*acc)[4], const float* bias,
                                             int w, int lane) {
    int g = lane >> 2, tig = lane & 3;
#pragma unroll
    for (int rt = 0; rt < 2; rt++)
#pragma unroll
        for (int tt = 0; tt < 16; tt++) {
            int n0 = tt*8 + tig*2;
            float bz0 = bias[n0], bz1 = bias[n0+1];
            float* r0 = sA + (32*w + 16*rt + g)*SROW + n0;
            const float* a = acc[rt*16 + tt];
            *(float2*)r0            = make_float2(a[0]+bz0, a[1]+bz1);
            *(float2*)(r0 + 8*SROW) = make_float2(a[2]+bz0, a[3]+bz1);
        }
}

// ---------------- zero stats ----------------
__global__ void k_zero() {
    int i = blockIdx.x * blockDim.x + threadIdx.x;
    const int n = 2*2*32*HID;
    double* p = &g_stat[0][0][0][0];
    for (; i < n; i += gridDim.x * blockDim.x) p[i] = 0.0;
}

// ---------------- pos -> float4 ----------------
__global__ void k_pos4(const float* __restrict__ pos) {
    int i = blockIdx.x * blockDim.x + threadIdx.x;
    if (i < BB*NPTS)
        g_pos4[i] = make_float4(pos[3*i], pos[3*i+1], pos[3*i+2], 0.f);
}

// ---------------- weight fragment prep (bf16 hi/lo, m16n8k16 B layout) ----------------
__global__ void k_wprep(const float* __restrict__ W, int K, int nslab, int which) {
    uint32_t* dst = (which == 0) ? g_WF0 : (which == 1) ? g_WF1 : g_WF2;
    int i = blockIdx.x * blockDim.x + threadIdx.x;
    int tot = nslab * 2048;
    if (i >= tot) return;
    int s = i >> 11, r = i & 2047;
    int reg = r & 1, lane = (r >> 1) & 31, tt = (r >> 6) & 15, kk = (r >> 10) & 1;
    int k0 = s*32 + kk*16 + reg*8 + (lane & 3)*2;
    int n  = tt*8 + (lane >> 2);
    float v0 = (k0     < K) ? W[k0*HID + n]     : 0.f;
    float v1 = (k0 + 1 < K) ? W[(k0+1)*HID + n] : 0.f;
    uint32_t h, l;
    split2(v0, v1, h, l);
    dst[s*4096 + r]        = h;
    dst[s*4096 + 2048 + r] = l;
}

// ---------------- farthest point sampling (1 sync/iter, double-buffered) ----------------
__global__ void __launch_bounds__(1024) k_fps(const float* __restrict__ pos,
                                              float* __restrict__ octr,
                                              float* __restrict__ obat) {
    int b = blockIdx.x, t = threadIdx.x;
    const float* p = pos + (size_t)b * NPTS * 3;
    float px[4], py[4], pz[4], md[4];
#pragma unroll
    for (int j = 0; j < 4; j++) {
        int i = t + j * 1024;
        px[j] = p[3*i]; py[j] = p[3*i+1]; pz[j] = p[3*i+2];
        md[j] = __int_as_float(0x7f800000);
    }
    __shared__ unsigned svk[2][32];
    __shared__ unsigned svi[2][32];
    int lane = t & 31, w = t >> 5;
    int last = 0;
    for (int s = 0; s < SS; s++) {
        float qx = p[3*last], qy = p[3*last+1], qz = p[3*last+2];
        if (t == 0) {
            int o = b*SS + s;
            g_ctr[o*3] = qx; g_ctr[o*3+1] = qy; g_ctr[o*3+2] = qz;
            if (octr) { octr[o*3] = qx; octr[o*3+1] = qy; octr[o*3+2] = qz; }
            if (obat) obat[o] = (float)b;
        }
        float bv = -1.f; int bi = 0;
#pragma unroll
        for (int j = 0; j < 4; j++) {
            float dx = px[j]-qx, dy = py[j]-qy, dz = pz[j]-qz;
            float d = fmaf(dz, dz, fmaf(dy, dy, __fmul_rn(dx, dx)));
            md[j] = fminf(md[j], d);
            if (md[j] > bv) { bv = md[j]; bi = t + j*1024; }  // strict >: lowest idx wins
        }
        // bv >= 0: fp bits order-isomorphic to unsigned
        unsigned key  = __float_as_uint(bv);
        unsigned vmax = __reduce_max_sync(0xffffffffu, key);
        unsigned cand = (key == vmax) ? (unsigned)bi : 0xffffffffu;
        unsigned imin = __reduce_min_sync(0xffffffffu, cand);
        int buf = s & 1;
        if (lane == 0) { svk[buf][w] = vmax; svi[buf][w] = imin; }
        __syncthreads();
        // every warp redundantly reduces the 32 warp results (uniform answer)
        unsigned k2 = svk[buf][lane], i2 = svi[buf][lane];
        unsigned vm2 = __reduce_max_sync(0xffffffffu, k2);
        unsigned c2  = (k2 == vm2) ? i2 : 0xffffffffu;
        last = (int)__reduce_min_sync(0xffffffffu, c2);
    }
}

// ---------------- radius-capped kNN (known-good) ----------------
__global__ void __launch_bounds__(128) k_nbr() {
    int c = blockIdx.x, t = threadIdx.x;
    int b = c >> 11;
    __shared__ float sd[MAXC];
    __shared__ int   sid[MAXC];
    __shared__ int   hist[128];
    __shared__ int   sc, so, s_tb, s_m, tc;
    __shared__ float td[256];
    __shared__ int   tdi[256];
    __shared__ int   wtot[4];
    if (t == 0) { sc = 0; so = 0; tc = 0; }
    hist[t] = 0;
    float cx = g_ctr[c*3], cy = g_ctr[c*3+1], cz = g_ctr[c*3+2];
    __syncthreads();
    for (int i = t; i < NPTS; i += 128) {
        float4 P = g_pos4[b*NPTS + i];
        float dx = P.x-cx, dy = P.y-cy, dz = P.z-cz;
        float d = fmaf(dz, dz, fmaf(dy, dy, __fmul_rn(dx, dx)));
        if (d <= R2F) {
            int k = atomicAdd(&sc, 1);
            if (k < MAXC) { sd[k] = d; sid[k] = i; }
        }
    }
    __syncthreads();
    int cnt = min(sc, MAXC);
    if (cnt <= KNB) {
        if (t < cnt) g_nbr[c*KNB + t] = sid[t];
        if (t == 0) g_cnt[c] = cnt;
        return;
    }
    const float bsc = 128.0f / R2F;
    for (int i = t; i < cnt; i += 128) {
        int bk = min(127, (int)(sd[i] * bsc));
        atomicAdd(&hist[bk], 1);
    }
    __syncthreads();
    {
        int lane = t & 31, w = t >> 5;
        int h = hist[t], v = h;
#pragma unroll
        for (int o = 1; o < 32; o <<= 1) {
            int u = __shfl_up_sync(0xffffffffu, v, o);
            if (lane >= o) v += u;
        }
        if (lane == 31) wtot[w] = v;
        __syncthreads();
        int base = 0;
        for (int k2 = 0; k2 < w; k2++) base += wtot[k2];
        int incl = v + base, excl = incl - h;
        if (incl >= KNB && excl < KNB) { s_tb = t; s_m = excl; }
    }
    __syncthreads();
    int tb = s_tb, m = s_m;
    for (int i = t; i < cnt; i += 128) {
        int bk = min(127, (int)(sd[i] * bsc));
        if (bk < tb) {
            int k = atomicAdd(&so, 1);
            g_nbr[c*KNB + k] = sid[i];
        } else if (bk == tb) {
            int k = atomicAdd(&tc, 1);
            if (k < 256) { td[k] = sd[i]; tdi[k] = sid[i]; }
        }
    }
    __syncthreads();
    int bn = min(tc, 256), rem = KNB - m;
    for (int i = t; i < bn; i += 128) {
        float di = td[i]; int ii = tdi[i];
        int rank = 0;
        for (int j2 = 0; j2 < bn; j2++) {
            float dj = td[j2]; int ij = tdi[j2];
            if (dj < di || (dj == di && ij < ii)) rank++;
        }
        if (rank < rem) {
            int k = atomicAdd(&so, 1);
            g_nbr[c*KNB + k] = tdi[i];
        }
    }
    if (t == 0) g_cnt[c] = KNB;
}

// ---------------- layer 0: gather -> GEMM -> H0 + stats ----------------
__global__ void __launch_bounds__(128, 2) k_l0(const float* __restrict__ x,
                                               const float* __restrict__ b0) {
    extern __shared__ float sm[];
    float*    sA   = sm;                         // 128*132 f32
    uint32_t* sB   = (uint32_t*)(sm + 128*SROW); // 4096 u32
    float*    bias = sm + 128*SROW + 4096;       // 128
    int t = threadIdx.x, w = t >> 5, lane = t & 31, blk = blockIdx.x;
    bias[t] = b0[t];

    // zero A staging (cols >=67 and invalid rows MUST be 0)
    {
        float4 z = make_float4(0.f, 0.f, 0.f, 0.f);
        for (int i = t; i < 128*33; i += 128)
            *(float4*)(sA + (i/33)*SROW + (i%33)*4) = z;
    }
    __syncthreads();

    // gather: row t = edge
    int c2 = blk*2 + (t >> 6), e = t & 63;
    int cnt_my = g_cnt[c2];
    if (e < cnt_my) {
        int j = g_nbr[c2*KNB + e];
        int bcl = c2 >> 11;
        const float4* xr = (const float4*)(x + (size_t)(bcl*NPTS + j)*CIN);
        float* row = sA + t*SROW;
#pragma unroll
        for (int q = 0; q < 16; q++)
            *(float4*)(row + 4*q) = xr[q];
        float4 P = g_pos4[bcl*NPTS + j];
        row[64] = P.x - g_ctr[c2*3];
        row[65] = P.y - g_ctr[c2*3+1];
        row[66] = P.z - g_ctr[c2*3+2];
    }

    float acc[32][4];
#pragma unroll
    for (int i = 0; i < 32; i++)
#pragma unroll
        for (int r = 0; r < 4; r++) acc[i][r] = 0.f;

#pragma unroll 1
    for (int s = 0; s < 3; s++) {
        __syncthreads();
        const float4* src = (const float4*)(g_WF0 + s*4096);
        float4* dst = (float4*)sB;
        for (int i = t; i < 1024; i += 128) dst[i] = src[i];
        __syncthreads();
        gemm_slab(sA, sB, acc, w, lane, s*32, (s < 2) ? 2 : 1);  // slab2: cols 64-79 only
    }

    epi_to_stage(sA, acc, bias, w, lane);
    __syncthreads();

    float4* dstH = (float4*)(g_H0 + (size_t)blk * 16384);
    for (int i = t; i < 4096; i += 128)
        dstH[i] = *(const float4*)(sA + (i >> 5)*SROW + (i & 31)*4);

    int cnt0 = g_cnt[blk*2], cnt1 = g_cnt[blk*2+1];
    float ssum = 0.f, ssq = 0.f;
    for (int r = 0; r < 128; r++) {
        bool val = (r & 63) < ((r >> 6) ? cnt1 : cnt0);
        float v = sA[r*SROW + t];
        if (val) { ssum += v; ssq = fmaf(v, v, ssq); }
    }
    atomicAdd(&g_stat[0][0][blk & 31][t], (double)ssum);
    atomicAdd(&g_stat[0][1][blk & 31][t], (double)ssq);
}

// ---------------- bn prepare ----------------
__global__ void k_prep(const float* __restrict__ gamma,
                       const float* __restrict__ beta, int layer) {
    int t = threadIdx.x;
    int local = 0;
    for (int i = t; i < BSZ; i += 128) local += g_cnt[i];
    __shared__ int sred[4];
    int lane = t & 31, w = t >> 5;
#pragma unroll
    for (int off = 16; off > 0; off >>= 1)
        local += __shfl_down_sync(0xffffffffu, local, off);
    if (lane == 0) sred[w] = local;
    __syncthreads();
    double cntd = (double)(sred[0] + sred[1] + sred[2] + sred[3]);
    double s = 0.0, q = 0.0;
    for (int k = 0; k < 32; k++) {
        s += g_stat[layer][0][k][t];
        q += g_stat[layer][1][k][t];
    }
    double mean = s / cntd;
    double var = q / cntd - mean * mean;
    if (var < 0.0) var = 0.0;
    double a = (double)gamma[t] * rsqrt(var + 1e-5);
    g_scale[layer][t] = (float)a;
    g_shift[layer][t] = (float)((double)beta[t] - mean * a);
}

// ---------------- layer 1: bnrelu(H0) -> GEMM -> H1 + stats ----------------
__global__ void __launch_bounds__(128, 2) k_l1(const float* __restrict__ b1) {
    extern __shared__ float sm[];
    float*    sA   = sm;
    uint32_t* sB   = (uint32_t*)(sm + 128*SROW);
    float*    bias = sm + 128*SROW + 4096;
    float*    sc   = bias + 128;
    float*    sh   = sc + 128;
    int t = threadIdx.x, w = t >> 5, lane = t & 31, blk = blockIdx.x;
    bias[t] = b1[t]; sc[t] = g_scale[0][t]; sh[t] = g_shift[0][t];
    __syncthreads();

    const float4* src = (const float4*)(g_H0 + (size_t)blk * 16384);
    for (int i = t; i < 4096; i += 128) {
        int row = i >> 5, c4 = (i & 31) * 4;
        float4 v = src[i];
        float4 z;
        z.x = fmaxf(0.f, fmaf(v.x, sc[c4+0], sh[c4+0]));
        z.y = fmaxf(0.f, fmaf(v.y, sc[c4+1], sh[c4+1]));
        z.z = fmaxf(0.f, fmaf(v.z, sc[c4+2], sh[c4+2]));
        z.w = fmaxf(0.f, fmaf(v.w, sc[c4+3], sh[c4+3]));
        *(float4*)(sA + row*SROW + c4) = z;
    }

    float acc[32][4];
#pragma unroll
    for (int i = 0; i < 32; i++)
#pragma unroll
        for (int r = 0; r < 4; r++) acc[i][r] = 0.f;

#pragma unroll 1
    for (int s = 0; s < 4; s++) {
        __syncthreads();
        const float4* wsrc = (const float4*)(g_WF1 + s*4096);
        float4* dst = (float4*)sB;
        for (int i = t; i < 1024; i += 128) dst[i] = wsrc[i];
        __syncthreads();
        gemm_slab(sA, sB, acc, w, lane, s*32, 2);
    }

    epi_to_stage(sA, acc, bias, w, lane);
    __syncthreads();

    float4* dstH = (float4*)(g_H1 + (size_t)blk * 16384);
    for (int i = t; i < 4096; i += 128)
        dstH[i] = *(const float4*)(sA + (i >> 5)*SROW + (i & 31)*4);

    int cnt0 = g_cnt[blk*2], cnt1 = g_cnt[blk*2+1];
    float ssum = 0.f, ssq = 0.f;
    for (int r = 0; r < 128; r++) {
        bool val = (r & 63) < ((r >> 6) ? cnt1 : cnt0);
        float v = sA[r*SROW + t];
        if (val) { ssum += v; ssq = fmaf(v, v, ssq); }
    }
    atomicAdd(&g_stat[1][0][blk & 31][t], (double)ssum);
    atomicAdd(&g_stat[1][1][blk & 31][t], (double)ssq);
}

// ---------------- layer 2: bnrelu(H1) -> GEMM -> masked max -> out ----------------
__global__ void __launch_bounds__(128, 2) k_l2(const float* __restrict__ b2,
                                               float* __restrict__ outp) {
    extern __shared__ float sm[];
    float*    sA   = sm;
    uint32_t* sB   = (uint32_t*)(sm + 128*SROW);
    float*    bias = sm + 128*SROW + 4096;
    float*    sc   = bias + 128;
    float*    sh   = sc + 128;
    int t = threadIdx.x, w = t >> 5, lane = t & 31, blk = blockIdx.x;
    bias[t] = b2[t]; sc[t] = g_scale[1][t]; sh[t] = g_shift[1][t];
    __syncthreads();

    const float4* src = (const float4*)(g_H1 + (size_t)blk * 16384);
    for (int i = t; i < 4096; i += 128) {
        int row = i >> 5, c4 = (i & 31) * 4;
        float4 v = src[i];
        float4 z;
        z.x = fmaxf(0.f, fmaf(v.x, sc[c4+0], sh[c4+0]));
        z.y = fmaxf(0.f, fmaf(v.y, sc[c4+1], sh[c4+1]));
        z.z = fmaxf(0.f, fmaf(v.z, sc[c4+2], sh[c4+2]));
        z.w = fmaxf(0.f, fmaf(v.w, sc[c4+3], sh[c4+3]));
        *(float4*)(sA + row*SROW + c4) = z;
    }

    float acc[32][4];
#pragma unroll
    for (int i = 0; i < 32; i++)
#pragma unroll
        for (int r = 0; r < 4; r++) acc[i][r] = 0.f;

#pragma unroll 1
    for (int s = 0; s < 4; s++) {
        __syncthreads();
        const float4* wsrc = (const float4*)(g_WF2 + s*4096);
        float4* dst = (float4*)sB;
        for (int i = t; i < 1024; i += 128) dst[i] = wsrc[i];
        __syncthreads();
        gemm_slab(sA, sB, acc, w, lane, s*32, 2);
    }

    epi_to_stage(sA, acc, bias, w, lane);
    __syncthreads();

    int cnt0 = g_cnt[blk*2], cnt1 = g_cnt[blk*2+1];
    const float NINF = __int_as_float(0xff800000);
    float m0 = NINF, m1 = NINF;
    for (int r = 0; r < 64; r++)
        if (r < cnt0) m0 = fmaxf(m0, sA[r*SROW + t]);
    for (int r = 64; r < 128; r++)
        if ((r - 64) < cnt1) m1 = fmaxf(m1, sA[r*SROW + t]);
    outp[(size_t)(blk*2)     * HID + t] = m0;
    outp[(size_t)(blk*2 + 1) * HID + t] = m1;
}

// ---------------- launch ----------------
extern "C" void kernel_launch(void* const* d_in, const int* in_sizes, int n_in,
                              void* d_out, int out_size) {
    const float* x   = (const float*)d_in[0];
    const float* pos = (const float*)d_in[1];
    const float* W0  = (const float*)d_in[3];
    const float* b0  = (const float*)d_in[4];
    const float* g0  = (const float*)d_in[5];
    const float* be0 = (const float*)d_in[6];
    const float* W1  = (const float*)d_in[7];
    const float* b1  = (const float*)d_in[8];
    const float* g1  = (const float*)d_in[9];
    const float* be1 = (const float*)d_in[10];
    const float* W2  = (const float*)d_in[11];
    const float* b2  = (const float*)d_in[12];
    float* out = (float*)d_out;

    float* octr = (out_size >= BSZ*HID + BSZ*3) ? out + (size_t)BSZ*HID : nullptr;
    float* obat = (out_size >= BSZ*HID + BSZ*3 + BSZ) ? out + (size_t)BSZ*131 : nullptr;

    int smB = (128*SROW + 4096 + 384) * 4;   // 85,504 B
    cudaFuncSetAttribute(k_l0, cudaFuncAttributeMaxDynamicSharedMemorySize, smB);
    cudaFuncSetAttribute(k_l1, cudaFuncAttributeMaxDynamicSharedMemorySize, smB);
    cudaFuncSetAttribute(k_l2, cudaFuncAttributeMaxDynamicSharedMemorySize, smB);

    k_zero<<<32, 256>>>();
    k_pos4<<<(BB*NPTS + 255)/256, 256>>>(pos);
    k_wprep<<<(3*2048 + 255)/256, 256>>>(W0, 67, 3, 0);
    k_wprep<<<(4*2048 + 255)/256, 256>>>(W1, HID, 4, 1);
    k_wprep<<<(4*2048 + 255)/256, 256>>>(W2, HID, 4, 2);
    k_fps<<<BB, 1024>>>(pos, octr, obat);
    k_nbr<<<BSZ, 128>>>();
    k_l0<<<NBLK, 128, smB>>>(x, b0);
    k_prep<<<1, 128>>>(g0, be0, 0);
    k_l1<<<NBLK, 128, smB>>>(b1);
    k_prep<<<1, 128>>>(g1, be1, 1);
    k_l2<<<NBLK, 128, smB>>>(b2, out);
}

// round 11
// speedup vs baseline: 2.7538x; 1.0126x over previous
#include <cuda_runtime.h>
#include <cuda_bf16.h>
#include <cstdint>
#include <cstddef>

#define BB   8
#define NPTS 4096
#define SS   2048
#define KNB  64
#define CIN  64
#define HID  128
#define BSZ  (BB*SS)
#define R2F  0.04f
#define MAXC 1024
#define NBLK (BSZ/2)          // 2 centroids per GEMM block
#define SROW 132              // fp32 staging row stride

// ---------------- device scratch ----------------
__device__ float  g_ctr[BSZ*3];
__device__ int    g_nbr[BSZ*KNB];
__device__ int    g_cnt[BSZ];
__device__ float4 g_pos4[BB*NPTS];
__device__ float  g_H0[(size_t)NBLK*128*HID];
__device__ float  g_H1[(size_t)NBLK*128*HID];
__device__ double g_stat[2][2][32][HID];
__device__ float  g_scale[2][HID];
__device__ float  g_shift[2][HID];
// pair-fragment bf16 hi/lo weights: per slab 4096 u32 = [hi 2048 | lo 2048]
// hi u32 index: ((kk*8 + tth)*32 + lane)*4 + reg + 2*(tt&1),  tt = 2*tth + (tt&1)
__device__ uint32_t g_WF0[3*4096];
__device__ uint32_t g_WF1[4*4096];
__device__ uint32_t g_WF2[4*4096];

// ---------------- helpers ----------------
__device__ __forceinline__ uint32_t smem_u32(const void* p) {
    uint32_t a;
    asm("{ .reg .u64 t; cvta.to.shared.u64 t, %1; cvt.u32.u64 %0, t; }" : "=r"(a) : "l"(p));
    return a;
}
__device__ __forceinline__ void cp16(void* dst, const void* src) {
    asm volatile("cp.async.ca.shared.global [%0], [%1], 16;"
                 :: "r"(smem_u32(dst)), "l"(src) : "memory");
}
#define CP_COMMIT() asm volatile("cp.async.commit_group;" ::: "memory")
#define CP_WAIT0()  asm volatile("cp.async.wait_group 0;" ::: "memory")

__device__ __forceinline__ void split2(float x, float y, uint32_t& h, uint32_t& l) {
    __nv_bfloat162 hb = __floats2bfloat162_rn(x, y);
    h = *(uint32_t*)&hb;
    float lx = x - __bfloat162float(hb.x);
    float ly = y - __bfloat162float(hb.y);
    __nv_bfloat162 lb = __floats2bfloat162_rn(lx, ly);
    l = *(uint32_t*)&lb;
}

__device__ __forceinline__ void mma16(float* c, uint32_t a0, uint32_t a1, uint32_t a2,
                                      uint32_t a3, uint32_t b0, uint32_t b1) {
    asm volatile("mma.sync.aligned.m16n8k16.row.col.f32.bf16.bf16.f32 "
        "{%0,%1,%2,%3}, {%4,%5,%6,%7}, {%8,%9}, {%0,%1,%2,%3};\n"
        : "+f"(c[0]), "+f"(c[1]), "+f"(c[2]), "+f"(c[3])
        : "r"(a0), "r"(a1), "r"(a2), "r"(a3), "r"(b0), "r"(b1));
}

// GEMM slab: A from row-major fp32 staging (bf16 hi/lo split in regs),
// B pair-fragment images (uint4 = b regs of tt, tt+1).
__device__ __forceinline__ void gemm_slab(const float* sA, const uint32_t* sB,
                                          float (*acc)[4], int w, int lane, int scol,
                                          int nkk) {
    int g = lane >> 2, tig = lane & 3;
#pragma unroll 1
    for (int kk = 0; kk < nkk; kk++) {
        uint32_t ah[2][4], al[2][4];
#pragma unroll
        for (int rt = 0; rt < 2; rt++) {
            const float* base = sA + (32*w + 16*rt + g)*SROW + scol + kk*16 + 2*tig;
            float2 v00 = *(const float2*)(base);
            float2 v01 = *(const float2*)(base + 8);
            float2 v10 = *(const float2*)(base + 8*SROW);
            float2 v11 = *(const float2*)(base + 8*SROW + 8);
            split2(v00.x, v00.y, ah[rt][0], al[rt][0]);
            split2(v10.x, v10.y, ah[rt][1], al[rt][1]);
            split2(v01.x, v01.y, ah[rt][2], al[rt][2]);
            split2(v11.x, v11.y, ah[rt][3], al[rt][3]);
        }
        const uint32_t* bh = sB + kk*1024;
        const uint32_t* bl = sB + 2048 + kk*1024;
#pragma unroll
        for (int tth = 0; tth < 8; tth++) {
            uint4 b = *(const uint4*)&bh[(tth*32 + lane)*4];
            mma16(acc[2*tth],      ah[0][0], ah[0][1], ah[0][2], ah[0][3], b.x, b.y);
            mma16(acc[16+2*tth],   ah[1][0], ah[1][1], ah[1][2], ah[1][3], b.x, b.y);
            mma16(acc[2*tth],      al[0][0], al[0][1], al[0][2], al[0][3], b.x, b.y);
            mma16(acc[16+2*tth],   al[1][0], al[1][1], al[1][2], al[1][3], b.x, b.y);
            mma16(acc[2*tth+1],    ah[0][0], ah[0][1], ah[0][2], ah[0][3], b.z, b.w);
            mma16(acc[16+2*tth+1], ah[1][0], ah[1][1], ah[1][2], ah[1][3], b.z, b.w);
            mma16(acc[2*tth+1],    al[0][0], al[0][1], al[0][2], al[0][3], b.z, b.w);
            mma16(acc[16+2*tth+1], al[1][0], al[1][1], al[1][2], al[1][3], b.z, b.w);
        }
#pragma unroll
        for (int tth = 0; tth < 8; tth++) {
            uint4 b = *(const uint4*)&bl[(tth*32 + lane)*4];
            mma16(acc[2*tth],      ah[0][0], ah[0][1], ah[0][2], ah[0][3], b.x, b.y);
            mma16(acc[16+2*tth],   ah[1][0], ah[1][1], ah[1][2], ah[1][3], b.x, b.y);
            mma16(acc[2*tth+1],    ah[0][0], ah[0][1], ah[0][2], ah[0][3], b.z, b.w);
            mma16(acc[16+2*tth+1], ah[1][0], ah[1][1], ah[1][2], ah[1][3], b.z, b.w);
        }
    }
}

// async B slab copy (each thread 8x uint4)
__device__ __forceinline__ void stageB(uint32_t* buf, const uint32_t* src, int t) {
#pragma unroll
    for (int i = 0; i < 8; i++) {
        int idx = (t + i*128) * 4;
        cp16(buf + idx, src + idx);
    }
    CP_COMMIT();
}

// acc -> (+bias) -> staging rows (warp writes only its own rows)
__device__ __forceinline__ void epi_to_stage(float* sA, float (*acc)[4], const float* bias,
                                             int w, int lane) {
    int g = lane >> 2, tig = lane & 3;
#pragma unroll
    for (int rt = 0; rt < 2; rt++)
#pragma unroll
        for (int tt = 0; tt < 16; tt++) {
            int n0 = tt*8 + tig*2;
            float bz0 = bias[n0], bz1 = bias[n0+1];
            float* r0 = sA + (32*w + 16*rt + g)*SROW + n0;
            const float* a = acc[rt*16 + tt];
            *(float2*)r0            = make_float2(a[0]+bz0, a[1]+bz1);
            *(float2*)(r0 + 8*SROW) = make_float2(a[2]+bz0, a[3]+bz1);
        }
}

// ---------------- zero stats ----------------
__global__ void k_zero() {
    int i = blockIdx.x * blockDim.x + threadIdx.x;
    const int n = 2*2*32*HID;
    double* p = &g_stat[0][0][0][0];
    for (; i < n; i += gridDim.x * blockDim.x) p[i] = 0.0;
}

// ---------------- pos -> float4 ----------------
__global__ void k_pos4(const float* __restrict__ pos) {
    int i = blockIdx.x * blockDim.x + threadIdx.x;
    if (i < BB*NPTS)
        g_pos4[i] = make_float4(pos[3*i], pos[3*i+1], pos[3*i+2], 0.f);
}

// ---------------- weight fragment prep (bf16 hi/lo, paired tt layout) ----------------
__global__ void k_wprep(const float* __restrict__ W, int K, int nslab, int which) {
    uint32_t* dst = (which == 0) ? g_WF0 : (which == 1) ? g_WF1 : g_WF2;
    int i = blockIdx.x * blockDim.x + threadIdx.x;
    int tot = nslab * 2048;
    if (i >= tot) return;
    int s = i >> 11, r = i & 2047;
    int q = r & 3, lane = (r >> 2) & 31, tth = (r >> 7) & 7, kk = (r >> 10) & 1;
    int reg = q & 1, tto = q >> 1;
    int tt = tth*2 + tto;
    int k0 = s*32 + kk*16 + reg*8 + (lane & 3)*2;
    int n  = tt*8 + (lane >> 2);
    float v0 = (k0     < K) ? W[k0*HID + n]     : 0.f;
    float v1 = (k0 + 1 < K) ? W[(k0+1)*HID + n] : 0.f;
    uint32_t h, l;
    split2(v0, v1, h, l);
    dst[s*4096 + r]        = h;
    dst[s*4096 + 2048 + r] = l;
}

// ---------------- farthest point sampling (1 sync/iter) ----------------
__global__ void __launch_bounds__(1024) k_fps(const float* __restrict__ pos,
                                              float* __restrict__ octr,
                                              float* __restrict__ obat) {
    int b = blockIdx.x, t = threadIdx.x;
    const float* p = pos + (size_t)b * NPTS * 3;
    float px[4], py[4], pz[4], md[4];
#pragma unroll
    for (int j = 0; j < 4; j++) {
        int i = t + j * 1024;
        px[j] = p[3*i]; py[j] = p[3*i+1]; pz[j] = p[3*i+2];
        md[j] = __int_as_float(0x7f800000);
    }
    __shared__ unsigned svk[2][32];
    __shared__ unsigned svi[2][32];
    int lane = t & 31, w = t >> 5;
    int last = 0;
    for (int s = 0; s < SS; s++) {
        float qx = p[3*last], qy = p[3*last+1], qz = p[3*last+2];
        if (t == 0) {
            int o = b*SS + s;
            g_ctr[o*3] = qx; g_ctr[o*3+1] = qy; g_ctr[o*3+2] = qz;
            if (octr) { octr[o*3] = qx; octr[o*3+1] = qy; octr[o*3+2] = qz; }
            if (obat) obat[o] = (float)b;
        }
        float bv = -1.f; int bi = 0;
#pragma unroll
        for (int j = 0; j < 4; j++) {
            float dx = px[j]-qx, dy = py[j]-qy, dz = pz[j]-qz;
            float d = fmaf(dz, dz, fmaf(dy, dy, __fmul_rn(dx, dx)));
            md[j] = fminf(md[j], d);
            if (md[j] > bv) { bv = md[j]; bi = t + j*1024; }  // strict >: lowest idx wins
        }
        unsigned key  = __float_as_uint(bv);
        unsigned vmax = __reduce_max_sync(0xffffffffu, key);
        unsigned cand = (key == vmax) ? (unsigned)bi : 0xffffffffu;
        unsigned imin = __reduce_min_sync(0xffffffffu, cand);
        int buf = s & 1;
        if (lane == 0) { svk[buf][w] = vmax; svi[buf][w] = imin; }
        __syncthreads();
        unsigned k2 = svk[buf][lane], i2 = svi[buf][lane];
        unsigned vm2 = __reduce_max_sync(0xffffffffu, k2);
        unsigned c2  = (k2 == vm2) ? i2 : 0xffffffffu;
        last = (int)__reduce_min_sync(0xffffffffu, c2);
    }
}

// ---------------- radius-capped kNN (known-good) ----------------
__global__ void __launch_bounds__(128) k_nbr() {
    int c = blockIdx.x, t = threadIdx.x;
    int b = c >> 11;
    __shared__ float sd[MAXC];
    __shared__ int   sid[MAXC];
    __shared__ int   hist[128];
    __shared__ int   sc, so, s_tb, s_m, tc;
    __shared__ float td[256];
    __shared__ int   tdi[256];
    __shared__ int   wtot[4];
    if (t == 0) { sc = 0; so = 0; tc = 0; }
    hist[t] = 0;
    float cx = g_ctr[c*3], cy = g_ctr[c*3+1], cz = g_ctr[c*3+2];
    __syncthreads();
    for (int i = t; i < NPTS; i += 128) {
        float4 P = g_pos4[b*NPTS + i];
        float dx = P.x-cx, dy = P.y-cy, dz = P.z-cz;
        float d = fmaf(dz, dz, fmaf(dy, dy, __fmul_rn(dx, dx)));
        if (d <= R2F) {
            int k = atomicAdd(&sc, 1);
            if (k < MAXC) { sd[k] = d; sid[k] = i; }
        }
    }
    __syncthreads();
    int cnt = min(sc, MAXC);
    if (cnt <= KNB) {
        if (t < cnt) g_nbr[c*KNB + t] = sid[t];
        if (t == 0) g_cnt[c] = cnt;
        return;
    }
    const float bsc = 128.0f / R2F;
    for (int i = t; i < cnt; i += 128) {
        int bk = min(127, (int)(sd[i] * bsc));
        atomicAdd(&hist[bk], 1);
    }
    __syncthreads();
    {
        int lane = t & 31, w = t >> 5;
        int h = hist[t], v = h;
#pragma unroll
        for (int o = 1; o < 32; o <<= 1) {
            int u = __shfl_up_sync(0xffffffffu, v, o);
            if (lane >= o) v += u;
        }
        if (lane == 31) wtot[w] = v;
        __syncthreads();
        int base = 0;
        for (int k2 = 0; k2 < w; k2++) base += wtot[k2];
        int incl = v + base, excl = incl - h;
        if (incl >= KNB && excl < KNB) { s_tb = t; s_m = excl; }
    }
    __syncthreads();
    int tb = s_tb, m = s_m;
    for (int i = t; i < cnt; i += 128) {
        int bk = min(127, (int)(sd[i] * bsc));
        if (bk < tb) {
            int k = atomicAdd(&so, 1);
            g_nbr[c*KNB + k] = sid[i];
        } else if (bk == tb) {
            int k = atomicAdd(&tc, 1);
            if (k < 256) { td[k] = sd[i]; tdi[k] = sid[i]; }
        }
    }
    __syncthreads();
    int bn = min(tc, 256), rem = KNB - m;
    for (int i = t; i < bn; i += 128) {
        float di = td[i]; int ii = tdi[i];
        int rank = 0;
        for (int j2 = 0; j2 < bn; j2++) {
            float dj = td[j2]; int ij = tdi[j2];
            if (dj < di || (dj == di && ij < ii)) rank++;
        }
        if (rank < rem) {
            int k = atomicAdd(&so, 1);
            g_nbr[c*KNB + k] = tdi[i];
        }
    }
    if (t == 0) g_cnt[c] = KNB;
}

// ---------------- layer 0: gather -> GEMM -> H0 + stats ----------------
__global__ void __launch_bounds__(128, 2) k_l0(const float* __restrict__ x,
                                               const float* __restrict__ b0) {
    extern __shared__ float sm[];
    float*    sA   = sm;                         // 128*132 f32
    uint32_t* sB0  = (uint32_t*)(sm + 128*SROW); // 4096 u32
    uint32_t* sB1  = sB0 + 4096;
    float*    bias = sm + 128*SROW + 8192;       // 128
    int t = threadIdx.x, w = t >> 5, lane = t & 31, blk = blockIdx.x;
    bias[t] = b0[t];

    stageB(sB0, g_WF0, t);   // slab 0 in flight

    // own-row gather: thread t fills row t cols 0..79 (rest never read in L0)
    int c2 = blk*2 + (t >> 6), e = t & 63;
    int cnt_my = g_cnt[c2];
    float* row = sA + t*SROW;
    float4 z4 = make_float4(0.f, 0.f, 0.f, 0.f);
    if (e < cnt_my) {
        int j = g_nbr[c2*KNB + e];
        int bcl = c2 >> 11;
        const float4* xr = (const float4*)(x + (size_t)(bcl*NPTS + j)*CIN);
#pragma unroll
        for (int q = 0; q < 16; q++)
            *(float4*)(row + 4*q) = xr[q];
        float4 P = g_pos4[bcl*NPTS + j];
        row[64] = P.x - g_ctr[c2*3];
        row[65] = P.y - g_ctr[c2*3+1];
        row[66] = P.z - g_ctr[c2*3+2];
        row[67] = 0.f;
        *(float4*)(row + 68) = z4;
        *(float4*)(row + 72) = z4;
        *(float4*)(row + 76) = z4;
    } else {
#pragma unroll
        for (int q = 0; q < 20; q++)
            *(float4*)(row + 4*q) = z4;
    }

    float acc[32][4];
#pragma unroll
    for (int i = 0; i < 32; i++)
#pragma unroll
        for (int r = 0; r < 4; r++) acc[i][r] = 0.f;

    uint32_t* bufs[2] = { sB0, sB1 };
#pragma unroll 1
    for (int s = 0; s < 3; s++) {
        CP_WAIT0();
        __syncthreads();
        if (s + 1 < 3) stageB(bufs[(s+1)&1], g_WF0 + (s+1)*4096, t);
        gemm_slab(sA, bufs[s&1], acc, w, lane, s*32, (s < 2) ? 2 : 1);
    }

    epi_to_stage(sA, acc, bias, w, lane);
    __syncthreads();

    float4* dstH = (float4*)(g_H0 + (size_t)blk * 16384);
    for (int i = t; i < 4096; i += 128)
        dstH[i] = *(const float4*)(sA + (i >> 5)*SROW + (i & 31)*4);

    int cnt0 = g_cnt[blk*2], cnt1 = g_cnt[blk*2+1];
    float ssum = 0.f, ssq = 0.f;
    for (int r = 0; r < 128; r++) {
        bool val = (r & 63) < ((r >> 6) ? cnt1 : cnt0);
        float v = sA[r*SROW + t];
        if (val) { ssum += v; ssq = fmaf(v, v, ssq); }
    }
    atomicAdd(&g_stat[0][0][blk & 31][t], (double)ssum);
    atomicAdd(&g_stat[0][1][blk & 31][t], (double)ssq);
}

// ---------------- bn prepare ----------------
__global__ void k_prep(const float* __restrict__ gamma,
                       const float* __restrict__ beta, int layer) {
    int t = threadIdx.x;
    int local = 0;
    for (int i = t; i < BSZ; i += 128) local += g_cnt[i];
    __shared__ int sred[4];
    int lane = t & 31, w = t >> 5;
#pragma unroll
    for (int off = 16; off > 0; off >>= 1)
        local += __shfl_down_sync(0xffffffffu, local, off);
    if (lane == 0) sred[w] = local;
    __syncthreads();
    double cntd = (double)(sred[0] + sred[1] + sred[2] + sred[3]);
    double s = 0.0, q = 0.0;
    for (int k = 0; k < 32; k++) {
        s += g_stat[layer][0][k][t];
        q += g_stat[layer][1][k][t];
    }
    double mean = s / cntd;
    double var = q / cntd - mean * mean;
    if (var < 0.0) var = 0.0;
    double a = (double)gamma[t] * rsqrt(var + 1e-5);
    g_scale[layer][t] = (float)a;
    g_shift[layer][t] = (float)((double)beta[t] - mean * a);
}

// ---------------- layer 1: bnrelu(H0) -> GEMM -> H1 + stats ----------------
__global__ void __launch_bounds__(128, 2) k_l1(const float* __restrict__ b1) {
    extern __shared__ float sm[];
    float*    sA   = sm;
    uint32_t* sB0  = (uint32_t*)(sm + 128*SROW);
    uint32_t* sB1  = sB0 + 4096;
    float*    bias = sm + 128*SROW + 8192;
    float*    sc   = bias + 128;
    float*    sh   = sc + 128;
    int t = threadIdx.x, w = t >> 5, lane = t & 31, blk = blockIdx.x;
    bias[t] = b1[t]; sc[t] = g_scale[0][t]; sh[t] = g_shift[0][t];

    stageB(sB0, g_WF1, t);
    __syncthreads();   // sc/sh visible for staging below

    const float4* src = (const float4*)(g_H0 + (size_t)blk * 16384);
    for (int i = t; i < 4096; i += 128) {
        int row = i >> 5, c4 = (i & 31) * 4;
        float4 v = src[i];
        float4 z;
        z.x = fmaxf(0.f, fmaf(v.x, sc[c4+0], sh[c4+0]));
        z.y = fmaxf(0.f, fmaf(v.y, sc[c4+1], sh[c4+1]));
        z.z = fmaxf(0.f, fmaf(v.z, sc[c4+2], sh[c4+2]));
        z.w = fmaxf(0.f, fmaf(v.w, sc[c4+3], sh[c4+3]));
        *(float4*)(sA + row*SROW + c4) = z;
    }

    float acc[32][4];
#pragma unroll
    for (int i = 0; i < 32; i++)
#pragma unroll
        for (int r = 0; r < 4; r++) acc[i][r] = 0.f;

    uint32_t* bufs[2] = { sB0, sB1 };
#pragma unroll 1
    for (int s = 0; s < 4; s++) {
        CP_WAIT0();
        __syncthreads();
        if (s + 1 < 4) stageB(bufs[(s+1)&1], g_WF1 + (s+1)*4096, t);
        gemm_slab(sA, bufs[s&1], acc, w, lane, s*32, 2);
    }

    epi_to_stage(sA, acc, bias, w, lane);
    __syncthreads();

    float4* dstH = (float4*)(g_H1 + (size_t)blk * 16384);
    for (int i = t; i < 4096; i += 128)
        dstH[i] = *(const float4*)(sA + (i >> 5)*SROW + (i & 31)*4);

    int cnt0 = g_cnt[blk*2], cnt1 = g_cnt[blk*2+1];
    float ssum = 0.f, ssq = 0.f;
    for (int r = 0; r < 128; r++) {
        bool val = (r & 63) < ((r >> 6) ? cnt1 : cnt0);
        float v = sA[r*SROW + t];
        if (val) { ssum += v; ssq = fmaf(v, v, ssq); }
    }
    atomicAdd(&g_stat[1][0][blk & 31][t], (double)ssum);
    atomicAdd(&g_stat[1][1][blk & 31][t], (double)ssq);
}

// ---------------- layer 2: bnrelu(H1) -> GEMM -> masked max -> out ----------------
__global__ void __launch_bounds__(128, 2) k_l2(const float* __restrict__ b2,
                                               float* __restrict__ outp) {
    extern __shared__ float sm[];
    float*    sA   = sm;
    uint32_t* sB0  = (uint32_t*)(sm + 128*SROW);
    uint32_t* sB1  = sB0 + 4096;
    float*    bias = sm + 128*SROW + 8192;
    float*    sc   = bias + 128;
    float*    sh   = sc + 128;
    int t = threadIdx.x, w = t >> 5, lane = t & 31, blk = blockIdx.x;
    bias[t] = b2[t]; sc[t] = g_scale[1][t]; sh[t] = g_shift[1][t];

    stageB(sB0, g_WF2, t);
    __syncthreads();

    const float4* src = (const float4*)(g_H1 + (size_t)blk * 16384);
    for (int i = t; i < 4096; i += 128) {
        int row = i >> 5, c4 = (i & 31) * 4;
        float4 v = src[i];
        float4 z;
        z.x = fmaxf(0.f, fmaf(v.x, sc[c4+0], sh[c4+0]));
        z.y = fmaxf(0.f, fmaf(v.y, sc[c4+1], sh[c4+1]));
        z.z = fmaxf(0.f, fmaf(v.z, sc[c4+2], sh[c4+2]));
        z.w = fmaxf(0.f, fmaf(v.w, sc[c4+3], sh[c4+3]));
        *(float4*)(sA + row*SROW + c4) = z;
    }

    float acc[32][4];
#pragma unroll
    for (int i = 0; i < 32; i++)
#pragma unroll
        for (int r = 0; r < 4; r++) acc[i][r] = 0.f;

    uint32_t* bufs[2] = { sB0, sB1 };
#pragma unroll 1
    for (int s = 0; s < 4; s++) {
        CP_WAIT0();
        __syncthreads();
        if (s + 1 < 4) stageB(bufs[(s+1)&1], g_WF2 + (s+1)*4096, t);
        gemm_slab(sA, bufs[s&1], acc, w, lane, s*32, 2);
    }

    epi_to_stage(sA, acc, bias, w, lane);
    __syncthreads();

    int cnt0 = g_cnt[blk*2], cnt1 = g_cnt[blk*2+1];
    const float NINF = __int_as_float(0xff800000);
    float m0 = NINF, m1 = NINF;
    for (int r = 0; r < 64; r++)
        if (r < cnt0) m0 = fmaxf(m0, sA[r*SROW + t]);
    for (int r = 64; r < 128; r++)
        if ((r - 64) < cnt1) m1 = fmaxf(m1, sA[r*SROW + t]);
    outp[(size_t)(blk*2)     * HID + t] = m0;
    outp[(size_t)(blk*2 + 1) * HID + t] = m1;
}

// ---------------- launch ----------------
extern "C" void kernel_launch(void* const* d_in, const int* in_sizes, int n_in,
                              void* d_out, int out_size) {
    const float* x   = (const float*)d_in[0];
    const float* pos = (const float*)d_in[1];
    const float* W0  = (const float*)d_in[3];
    const float* b0  = (const float*)d_in[4];
    const float* g0  = (const float*)d_in[5];
    const float* be0 = (const float*)d_in[6];
    const float* W1  = (const float*)d_in[7];
    const float* b1  = (const float*)d_in[8];
    const float* g1  = (const float*)d_in[9];
    const float* be1 = (const float*)d_in[10];
    const float* W2  = (const float*)d_in[11];
    const float* b2  = (const float*)d_in[12];
    float* out = (float*)d_out;

    float* octr = (out_size >= BSZ*HID + BSZ*3) ? out + (size_t)BSZ*HID : nullptr;
    float* obat = (out_size >= BSZ*HID + BSZ*3 + BSZ) ? out + (size_t)BSZ*131 : nullptr;

    int smB = (128*SROW + 8192 + 384) * 4;   // 101,888 B
    cudaFuncSetAttribute(k_l0, cudaFuncAttributeMaxDynamicSharedMemorySize, smB);
    cudaFuncSetAttribute(k_l1, cudaFuncAttributeMaxDynamicSharedMemorySize, smB);
    cudaFuncSetAttribute(k_l2, cudaFuncAttributeMaxDynamicSharedMemorySize, smB);

    k_zero<<<32, 256>>>();
    k_pos4<<<(BB*NPTS + 255)/256, 256>>>(pos);
    k_wprep<<<(3*2048 + 255)/256, 256>>>(W0, 67, 3, 0);
    k_wprep<<<(4*2048 + 255)/256, 256>>>(W1, HID, 4, 1);
    k_wprep<<<(4*2048 + 255)/256, 256>>>(W2, HID, 4, 2);
    k_fps<<<BB, 1024>>>(pos, octr, obat);
    k_nbr<<<BSZ, 128>>>();
    k_l0<<<NBLK, 128, smB>>>(x, b0);
    k_prep<<<1, 128>>>(g0, be0, 0);
    k_l1<<<NBLK, 128, smB>>>(b1);
    k_prep<<<1, 128>>>(g1, be1, 1);
    k_l2<<<NBLK, 128, smB>>>(b2, out);
}

// round 12
// speedup vs baseline: 3.1847x; 1.1565x over previous
#include <cuda_runtime.h>
#include <cuda_fp16.h>
#include <cstdint>
#include <cstddef>

#define BB   8
#define NPTS 4096
#define SS   2048
#define KNB  64
#define CIN  64
#define HID  128
#define BSZ  (BB*SS)
#define R2F  0.04f
#define MAXC 1024
#define NBLK (BSZ/2)          // 2 centroids per GEMM block
#define SROW 132              // fp32 staging row stride

// ---------------- device scratch ----------------
__device__ float  g_ctr[BSZ*3];
__device__ int    g_nbr[BSZ*KNB];
__device__ int    g_cnt[BSZ];
__device__ float4 g_pos4[BB*NPTS];
__device__ float  g_H0[(size_t)NBLK*128*HID];
__device__ float  g_H1[(size_t)NBLK*128*HID];
__device__ double g_stat[2][2][32][HID];
__device__ float  g_scale[2][HID];
__device__ float  g_shift[2][HID];
// pair-fragment fp16 hi/lo weights: per slab 4096 u32 = [hi 2048 | lo 2048]
__device__ uint32_t g_WF0[3*4096];
__device__ uint32_t g_WF1[4*4096];
__device__ uint32_t g_WF2[4*4096];

// ---------------- helpers ----------------
__device__ __forceinline__ uint32_t smem_u32(const void* p) {
    uint32_t a;
    asm("{ .reg .u64 t; cvta.to.shared.u64 t, %1; cvt.u32.u64 %0, t; }" : "=r"(a) : "l"(p));
    return a;
}
__device__ __forceinline__ void cp16(void* dst, const void* src) {
    asm volatile("cp.async.ca.shared.global [%0], [%1], 16;"
                 :: "r"(smem_u32(dst)), "l"(src) : "memory");
}
#define CP_COMMIT() asm volatile("cp.async.commit_group;" ::: "memory")
#define CP_WAIT0()  asm volatile("cp.async.wait_group 0;" ::: "memory")

__device__ __forceinline__ uint32_t h2(float x, float y) {
    __half2 v = __floats2half2_rn(x, y);
    return *(uint32_t*)&v;
}

__device__ __forceinline__ void mma16(float* c, uint32_t a0, uint32_t a1, uint32_t a2,
                                      uint32_t a3, uint32_t b0, uint32_t b1) {
    asm volatile("mma.sync.aligned.m16n8k16.row.col.f32.f16.f16.f32 "
        "{%0,%1,%2,%3}, {%4,%5,%6,%7}, {%8,%9}, {%0,%1,%2,%3};\n"
        : "+f"(c[0]), "+f"(c[1]), "+f"(c[2]), "+f"(c[3])
        : "r"(a0), "r"(a1), "r"(a2), "r"(a3), "r"(b0), "r"(b1));
}

// GEMM slab: A' = fp16(A) single conversion; B pair-fragment hi/lo images.
// D += A'*Bh + A'*Bl  (error = A truncation only, ~2^-12)
__device__ __forceinline__ void gemm_slab(const float* sA, const uint32_t* sB,
                                          float (*acc)[4], int w, int lane, int scol,
                                          int nkk) {
    int g = lane >> 2, tig = lane & 3;
#pragma unroll 1
    for (int kk = 0; kk < nkk; kk++) {
        uint32_t a[2][4];
#pragma unroll
        for (int rt = 0; rt < 2; rt++) {
            const float* base = sA + (32*w + 16*rt + g)*SROW + scol + kk*16 + 2*tig;
            float2 v00 = *(const float2*)(base);
            float2 v01 = *(const float2*)(base + 8);
            float2 v10 = *(const float2*)(base + 8*SROW);
            float2 v11 = *(const float2*)(base + 8*SROW + 8);
            a[rt][0] = h2(v00.x, v00.y);
            a[rt][1] = h2(v10.x, v10.y);
            a[rt][2] = h2(v01.x, v01.y);
            a[rt][3] = h2(v11.x, v11.y);
        }
        const uint32_t* bh = sB + kk*1024;
        const uint32_t* bl = sB + 2048 + kk*1024;
#pragma unroll
        for (int tth = 0; tth < 8; tth++) {
            uint4 b = *(const uint4*)&bh[(tth*32 + lane)*4];
            mma16(acc[2*tth],      a[0][0], a[0][1], a[0][2], a[0][3], b.x, b.y);
            mma16(acc[16+2*tth],   a[1][0], a[1][1], a[1][2], a[1][3], b.x, b.y);
            mma16(acc[2*tth+1],    a[0][0], a[0][1], a[0][2], a[0][3], b.z, b.w);
            mma16(acc[16+2*tth+1], a[1][0], a[1][1], a[1][2], a[1][3], b.z, b.w);
        }
#pragma unroll
        for (int tth = 0; tth < 8; tth++) {
            uint4 b = *(const uint4*)&bl[(tth*32 + lane)*4];
            mma16(acc[2*tth],      a[0][0], a[0][1], a[0][2], a[0][3], b.x, b.y);
            mma16(acc[16+2*tth],   a[1][0], a[1][1], a[1][2], a[1][3], b.x, b.y);
            mma16(acc[2*tth+1],    a[0][0], a[0][1], a[0][2], a[0][3], b.z, b.w);
            mma16(acc[16+2*tth+1], a[1][0], a[1][1], a[1][2], a[1][3], b.z, b.w);
        }
    }
}

// async B slab copy (each thread 8x uint4)
__device__ __forceinline__ void stageB(uint32_t* buf, const uint32_t* src, int t) {
#pragma unroll
    for (int i = 0; i < 8; i++) {
        int idx = (t + i*128) * 4;
        cp16(buf + idx, src + idx);
    }
    CP_COMMIT();
}

// acc -> (+bias) -> staging rows (warp writes only its own rows)
__device__ __forceinline__ void epi_to_stage(float* sA, float (*acc)[4], const float* bias,
                                             int w, int lane) {
    int g = lane >> 2, tig = lane & 3;
#pragma unroll
    for (int rt = 0; rt < 2; rt++)
#pragma unroll
        for (int tt = 0; tt < 16; tt++) {
            int n0 = tt*8 + tig*2;
            float bz0 = bias[n0], bz1 = bias[n0+1];
            float* r0 = sA + (32*w + 16*rt + g)*SROW + n0;
            const float* a = acc[rt*16 + tt];
            *(float2*)r0            = make_float2(a[0]+bz0, a[1]+bz1);
            *(float2*)(r0 + 8*SROW) = make_float2(a[2]+bz0, a[3]+bz1);
        }
}

// ---------------- zero stats ----------------
__global__ void k_zero() {
    int i = blockIdx.x * blockDim.x + threadIdx.x;
    const int n = 2*2*32*HID;
    double* p = &g_stat[0][0][0][0];
    for (; i < n; i += gridDim.x * blockDim.x) p[i] = 0.0;
}

// ---------------- pos -> float4 ----------------
__global__ void k_pos4(const float* __restrict__ pos) {
    int i = blockIdx.x * blockDim.x + threadIdx.x;
    if (i < BB*NPTS)
        g_pos4[i] = make_float4(pos[3*i], pos[3*i+1], pos[3*i+2], 0.f);
}

// ---------------- weight fragment prep (fp16 hi/lo, paired tt layout) ----------------
__global__ void k_wprep(const float* __restrict__ W, int K, int nslab, int which) {
    uint32_t* dst = (which == 0) ? g_WF0 : (which == 1) ? g_WF1 : g_WF2;
    int i = blockIdx.x * blockDim.x + threadIdx.x;
    int tot = nslab * 2048;
    if (i >= tot) return;
    int s = i >> 11, r = i & 2047;
    int q = r & 3, lane = (r >> 2) & 31, tth = (r >> 7) & 7, kk = (r >> 10) & 1;
    int reg = q & 1, tto = q >> 1;
    int tt = tth*2 + tto;
    int k0 = s*32 + kk*16 + reg*8 + (lane & 3)*2;
    int n  = tt*8 + (lane >> 2);
    float v0 = (k0     < K) ? W[k0*HID + n]     : 0.f;
    float v1 = (k0 + 1 < K) ? W[(k0+1)*HID + n] : 0.f;
    __half2 hh = __floats2half2_rn(v0, v1);
    float l0 = v0 - __half2float(__low2half(hh));
    float l1 = v1 - __half2float(__high2half(hh));
    dst[s*4096 + r]        = *(uint32_t*)&hh;
    dst[s*4096 + 2048 + r] = h2(l0, l1);
}

// ---------------- farthest point sampling (1 sync/iter, smem coords) ----------------
__global__ void __launch_bounds__(1024) k_fps(const float* __restrict__ pos,
                                              float* __restrict__ octr,
                                              float* __restrict__ obat) {
    extern __shared__ float fs[];    // sx[4096], sy[4096], sz[4096]
    float* sx = fs;
    float* sy = fs + NPTS;
    float* sz = fs + 2*NPTS;
    int b = blockIdx.x, t = threadIdx.x;
    const float* p = pos + (size_t)b * NPTS * 3;
    float px[4], py[4], pz[4], md[4];
#pragma unroll
    for (int j = 0; j < 4; j++) {
        int i = t + j * 1024;
        px[j] = p[3*i]; py[j] = p[3*i+1]; pz[j] = p[3*i+2];
        sx[i] = px[j]; sy[i] = py[j]; sz[i] = pz[j];
        md[j] = __int_as_float(0x7f800000);
    }
    __shared__ unsigned svk[2][32];
    __shared__ unsigned svi[2][32];
    int lane = t & 31, w = t >> 5;
    int last = 0;
    __syncthreads();
    for (int s = 0; s < SS; s++) {
        float qx = sx[last], qy = sy[last], qz = sz[last];
        if (t == 0) {
            int o = b*SS + s;
            g_ctr[o*3] = qx; g_ctr[o*3+1] = qy; g_ctr[o*3+2] = qz;
            if (octr) { octr[o*3] = qx; octr[o*3+1] = qy; octr[o*3+2] = qz; }
            if (obat) obat[o] = (float)b;
        }
        float bv = -1.f; int bi = 0;
#pragma unroll
        for (int j = 0; j < 4; j++) {
            float dx = px[j]-qx, dy = py[j]-qy, dz = pz[j]-qz;
            float d = fmaf(dz, dz, fmaf(dy, dy, __fmul_rn(dx, dx)));
            md[j] = fminf(md[j], d);
            if (md[j] > bv) { bv = md[j]; bi = t + j*1024; }  // strict >: lowest idx wins
        }
        unsigned key  = __float_as_uint(bv);
        unsigned vmax = __reduce_max_sync(0xffffffffu, key);
        unsigned cand = (key == vmax) ? (unsigned)bi : 0xffffffffu;
        unsigned imin = __reduce_min_sync(0xffffffffu, cand);
        int buf = s & 1;
        if (lane == 0) { svk[buf][w] = vmax; svi[buf][w] = imin; }
        __syncthreads();
        unsigned k2 = svk[buf][lane], i2 = svi[buf][lane];
        unsigned vm2 = __reduce_max_sync(0xffffffffu, k2);
        unsigned c2  = (k2 == vm2) ? i2 : 0xffffffffu;
        last = (int)__reduce_min_sync(0xffffffffu, c2);
    }
}

// ---------------- radius-capped kNN (known-good) ----------------
__global__ void __launch_bounds__(128) k_nbr() {
    int c = blockIdx.x, t = threadIdx.x;
    int b = c >> 11;
    __shared__ float sd[MAXC];
    __shared__ int   sid[MAXC];
    __shared__ int   hist[128];
    __shared__ int   sc, so, s_tb, s_m, tc;
    __shared__ float td[256];
    __shared__ int   tdi[256];
    __shared__ int   wtot[4];
    if (t == 0) { sc = 0; so = 0; tc = 0; }
    hist[t] = 0;
    float cx = g_ctr[c*3], cy = g_ctr[c*3+1], cz = g_ctr[c*3+2];
    __syncthreads();
    for (int i = t; i < NPTS; i += 128) {
        float4 P = g_pos4[b*NPTS + i];
        float dx = P.x-cx, dy = P.y-cy, dz = P.z-cz;
        float d = fmaf(dz, dz, fmaf(dy, dy, __fmul_rn(dx, dx)));
        if (d <= R2F) {
            int k = atomicAdd(&sc, 1);
            if (k < MAXC) { sd[k] = d; sid[k] = i; }
        }
    }
    __syncthreads();
    int cnt = min(sc, MAXC);
    if (cnt <= KNB) {
        if (t < cnt) g_nbr[c*KNB + t] = sid[t];
        if (t == 0) g_cnt[c] = cnt;
        return;
    }
    const float bsc = 128.0f / R2F;
    for (int i = t; i < cnt; i += 128) {
        int bk = min(127, (int)(sd[i] * bsc));
        atomicAdd(&hist[bk], 1);
    }
    __syncthreads();
    {
        int lane = t & 31, w = t >> 5;
        int h = hist[t], v = h;
#pragma unroll
        for (int o = 1; o < 32; o <<= 1) {
            int u = __shfl_up_sync(0xffffffffu, v, o);
            if (lane >= o) v += u;
        }
        if (lane == 31) wtot[w] = v;
        __syncthreads();
        int base = 0;
        for (int k2 = 0; k2 < w; k2++) base += wtot[k2];
        int incl = v + base, excl = incl - h;
        if (incl >= KNB && excl < KNB) { s_tb = t; s_m = excl; }
    }
    __syncthreads();
    int tb = s_tb, m = s_m;
    for (int i = t; i < cnt; i += 128) {
        int bk = min(127, (int)(sd[i] * bsc));
        if (bk < tb) {
            int k = atomicAdd(&so, 1);
            g_nbr[c*KNB + k] = sid[i];
        } else if (bk == tb) {
            int k = atomicAdd(&tc, 1);
            if (k < 256) { td[k] = sd[i]; tdi[k] = sid[i]; }
        }
    }
    __syncthreads();
    int bn = min(tc, 256), rem = KNB - m;
    for (int i = t; i < bn; i += 128) {
        float di = td[i]; int ii = tdi[i];
        int rank = 0;
        for (int j2 = 0; j2 < bn; j2++) {
            float dj = td[j2]; int ij = tdi[j2];
            if (dj < di || (dj == di && ij < ii)) rank++;
        }
        if (rank < rem) {
            int k = atomicAdd(&so, 1);
            g_nbr[c*KNB + k] = tdi[i];
        }
    }
    if (t == 0) g_cnt[c] = KNB;
}

// ---------------- layer 0: gather -> GEMM -> H0 + stats ----------------
__global__ void __launch_bounds__(128, 2) k_l0(const float* __restrict__ x,
                                               const float* __restrict__ b0) {
    extern __shared__ float sm[];
    float*    sA   = sm;                         // 128*132 f32
    uint32_t* sB0  = (uint32_t*)(sm + 128*SROW); // 4096 u32
    uint32_t* sB1  = sB0 + 4096;
    float*    bias = sm + 128*SROW + 8192;       // 128
    int t = threadIdx.x, w = t >> 5, lane = t & 31, blk = blockIdx.x;
    bias[t] = b0[t];

    stageB(sB0, g_WF0, t);   // slab 0 in flight

    // own-row gather: thread t fills row t cols 0..79 (rest never read in L0)
    int c2 = blk*2 + (t >> 6), e = t & 63;
    int cnt_my = g_cnt[c2];
    float* row = sA + t*SROW;
    float4 z4 = make_float4(0.f, 0.f, 0.f, 0.f);
    if (e < cnt_my) {
        int j = g_nbr[c2*KNB + e];
        int bcl = c2 >> 11;
        const float4* xr = (const float4*)(x + (size_t)(bcl*NPTS + j)*CIN);
#pragma unroll
        for (int q = 0; q < 16; q++)
            *(float4*)(row + 4*q) = xr[q];
        float4 P = g_pos4[bcl*NPTS + j];
        row[64] = P.x - g_ctr[c2*3];
        row[65] = P.y - g_ctr[c2*3+1];
        row[66] = P.z - g_ctr[c2*3+2];
        row[67] = 0.f;
        *(float4*)(row + 68) = z4;
        *(float4*)(row + 72) = z4;
        *(float4*)(row + 76) = z4;
    } else {
#pragma unroll
        for (int q = 0; q < 20; q++)
            *(float4*)(row + 4*q) = z4;
    }

    float acc[32][4];
#pragma unroll
    for (int i = 0; i < 32; i++)
#pragma unroll
        for (int r = 0; r < 4; r++) acc[i][r] = 0.f;

    uint32_t* bufs[2] = { sB0, sB1 };
#pragma unroll 1
    for (int s = 0; s < 3; s++) {
        CP_WAIT0();
        __syncthreads();
        if (s + 1 < 3) stageB(bufs[(s+1)&1], g_WF0 + (s+1)*4096, t);
        gemm_slab(sA, bufs[s&1], acc, w, lane, s*32, (s < 2) ? 2 : 1);
    }

    epi_to_stage(sA, acc, bias, w, lane);
    __syncthreads();

    float4* dstH = (float4*)(g_H0 + (size_t)blk * 16384);
    for (int i = t; i < 4096; i += 128)
        dstH[i] = *(const float4*)(sA + (i >> 5)*SROW + (i & 31)*4);

    int cnt0 = g_cnt[blk*2], cnt1 = g_cnt[blk*2+1];
    float ssum = 0.f, ssq = 0.f;
    for (int r = 0; r < 128; r++) {
        bool val = (r & 63) < ((r >> 6) ? cnt1 : cnt0);
        float v = sA[r*SROW + t];
        if (val) { ssum += v; ssq = fmaf(v, v, ssq); }
    }
    atomicAdd(&g_stat[0][0][blk & 31][t], (double)ssum);
    atomicAdd(&g_stat[0][1][blk & 31][t], (double)ssq);
}

// ---------------- bn prepare ----------------
__global__ void k_prep(const float* __restrict__ gamma,
                       const float* __restrict__ beta, int layer) {
    int t = threadIdx.x;
    int local = 0;
    for (int i = t; i < BSZ; i += 128) local += g_cnt[i];
    __shared__ int sred[4];
    int lane = t & 31, w = t >> 5;
#pragma unroll
    for (int off = 16; off > 0; off >>= 1)
        local += __shfl_down_sync(0xffffffffu, local, off);
    if (lane == 0) sred[w] = local;
    __syncthreads();
    double cntd = (double)(sred[0] + sred[1] + sred[2] + sred[3]);
    double s = 0.0, q = 0.0;
    for (int k = 0; k < 32; k++) {
        s += g_stat[layer][0][k][t];
        q += g_stat[layer][1][k][t];
    }
    double mean = s / cntd;
    double var = q / cntd - mean * mean;
    if (var < 0.0) var = 0.0;
    double a = (double)gamma[t] * rsqrt(var + 1e-5);
    g_scale[layer][t] = (float)a;
    g_shift[layer][t] = (float)((double)beta[t] - mean * a);
}

// ---------------- layer 1: bnrelu(H0) -> GEMM -> H1 + stats ----------------
__global__ void __launch_bounds__(128, 2) k_l1(const float* __restrict__ b1) {
    extern __shared__ float sm[];
    float*    sA   = sm;
    uint32_t* sB0  = (uint32_t*)(sm + 128*SROW);
    uint32_t* sB1  = sB0 + 4096;
    float*    bias = sm + 128*SROW + 8192;
    float*    sc   = bias + 128;
    float*    sh   = sc + 128;
    int t = threadIdx.x, w = t >> 5, lane = t & 31, blk = blockIdx.x;
    bias[t] = b1[t]; sc[t] = g_scale[0][t]; sh[t] = g_shift[0][t];

    stageB(sB0, g_WF1, t);
    __syncthreads();   // sc/sh visible for staging below

    const float4* src = (const float4*)(g_H0 + (size_t)blk * 16384);
    for (int i = t; i < 4096; i += 128) {
        int row = i >> 5, c4 = (i & 31) * 4;
        float4 v = src[i];
        float4 z;
        z.x = fmaxf(0.f, fmaf(v.x, sc[c4+0], sh[c4+0]));
        z.y = fmaxf(0.f, fmaf(v.y, sc[c4+1], sh[c4+1]));
        z.z = fmaxf(0.f, fmaf(v.z, sc[c4+2], sh[c4+2]));
        z.w = fmaxf(0.f, fmaf(v.w, sc[c4+3], sh[c4+3]));
        *(float4*)(sA + row*SROW + c4) = z;
    }

    float acc[32][4];
#pragma unroll
    for (int i = 0; i < 32; i++)
#pragma unroll
        for (int r = 0; r < 4; r++) acc[i][r] = 0.f;

    uint32_t* bufs[2] = { sB0, sB1 };
#pragma unroll 1
    for (int s = 0; s < 4; s++) {
        CP_WAIT0();
        __syncthreads();
        if (s + 1 < 4) stageB(bufs[(s+1)&1], g_WF1 + (s+1)*4096, t);
        gemm_slab(sA, bufs[s&1], acc, w, lane, s*32, 2);
    }

    epi_to_stage(sA, acc, bias, w, lane);
    __syncthreads();

    float4* dstH = (float4*)(g_H1 + (size_t)blk * 16384);
    for (int i = t; i < 4096; i += 128)
        dstH[i] = *(const float4*)(sA + (i >> 5)*SROW + (i & 31)*4);

    int cnt0 = g_cnt[blk*2], cnt1 = g_cnt[blk*2+1];
    float ssum = 0.f, ssq = 0.f;
    for (int r = 0; r < 128; r++) {
        bool val = (r & 63) < ((r >> 6) ? cnt1 : cnt0);
        float v = sA[r*SROW + t];
        if (val) { ssum += v; ssq = fmaf(v, v, ssq); }
    }
    atomicAdd(&g_stat[1][0][blk & 31][t], (double)ssum);
    atomicAdd(&g_stat[1][1][blk & 31][t], (double)ssq);
}

// ---------------- layer 2: bnrelu(H1) -> GEMM -> masked max -> out ----------------
__global__ void __launch_bounds__(128, 2) k_l2(const float* __restrict__ b2,
                                               float* __restrict__ outp) {
    extern __shared__ float sm[];
    float*    sA   = sm;
    uint32_t* sB0  = (uint32_t*)(sm + 128*SROW);
    uint32_t* sB1  = sB0 + 4096;
    float*    bias = sm + 128*SROW + 8192;
    float*    sc   = bias + 128;
    float*    sh   = sc + 128;
    int t = threadIdx.x, w = t >> 5, lane = t & 31, blk = blockIdx.x;
    bias[t] = b2[t]; sc[t] = g_scale[1][t]; sh[t] = g_shift[1][t];

    stageB(sB0, g_WF2, t);
    __syncthreads();

    const float4* src = (const float4*)(g_H1 + (size_t)blk * 16384);
    for (int i = t; i < 4096; i += 128) {
        int row = i >> 5, c4 = (i & 31) * 4;
        float4 v = src[i];
        float4 z;
        z.x = fmaxf(0.f, fmaf(v.x, sc[c4+0], sh[c4+0]));
        z.y = fmaxf(0.f, fmaf(v.y, sc[c4+1], sh[c4+1]));
        z.z = fmaxf(0.f, fmaf(v.z, sc[c4+2], sh[c4+2]));
        z.w = fmaxf(0.f, fmaf(v.w, sc[c4+3], sh[c4+3]));
        *(float4*)(sA + row*SROW + c4) = z;
    }

    float acc[32][4];
#pragma unroll
    for (int i = 0; i < 32; i++)
#pragma unroll
        for (int r = 0; r < 4; r++) acc[i][r] = 0.f;

    uint32_t* bufs[2] = { sB0, sB1 };
#pragma unroll 1
    for (int s = 0; s < 4; s++) {
        CP_WAIT0();
        __syncthreads();
        if (s + 1 < 4) stageB(bufs[(s+1)&1], g_WF2 + (s+1)*4096, t);
        gemm_slab(sA, bufs[s&1], acc, w, lane, s*32, 2);
    }

    epi_to_stage(sA, acc, bias, w, lane);
    __syncthreads();

    int cnt0 = g_cnt[blk*2], cnt1 = g_cnt[blk*2+1];
    const float NINF = __int_as_float(0xff800000);
    float m0 = NINF, m1 = NINF;
    for (int r = 0; r < 64; r++)
        if (r < cnt0) m0 = fmaxf(m0, sA[r*SROW + t]);
    for (int r = 64; r < 128; r++)
        if ((r - 64) < cnt1) m1 = fmaxf(m1, sA[r*SROW + t]);
    outp[(size_t)(blk*2)     * HID + t] = m0;
    outp[(size_t)(blk*2 + 1) * HID + t] = m1;
}

// ---------------- launch ----------------
extern "C" void kernel_launch(void* const* d_in, const int* in_sizes, int n_in,
                              void* d_out, int out_size) {
    const float* x   = (const float*)d_in[0];
    const float* pos = (const float*)d_in[1];
    const float* W0  = (const float*)d_in[3];
    const float* b0  = (const float*)d_in[4];
    const float* g0  = (const float*)d_in[5];
    const float* be0 = (const float*)d_in[6];
    const float* W1  = (const float*)d_in[7];
    const float* b1  = (const float*)d_in[8];
    const float* g1  = (const float*)d_in[9];
    const float* be1 = (const float*)d_in[10];
    const float* W2  = (const float*)d_in[11];
    const float* b2  = (const float*)d_in[12];
    float* out = (float*)d_out;

    float* octr = (out_size >= BSZ*HID + BSZ*3) ? out + (size_t)BSZ*HID : nullptr;
    float* obat = (out_size >= BSZ*HID + BSZ*3 + BSZ) ? out + (size_t)BSZ*131 : nullptr;

    int smB = (128*SROW + 8192 + 384) * 4;   // 101,888 B
    int smF = 3 * NPTS * 4;                  // 49,152 B
    cudaFuncSetAttribute(k_l0, cudaFuncAttributeMaxDynamicSharedMemorySize, smB);
    cudaFuncSetAttribute(k_l1, cudaFuncAttributeMaxDynamicSharedMemorySize, smB);
    cudaFuncSetAttribute(k_l2, cudaFuncAttributeMaxDynamicSharedMemorySize, smB);
    cudaFuncSetAttribute(k_fps, cudaFuncAttributeMaxDynamicSharedMemorySize, smF);

    // order chosen so ncu (-s 5 -c 1) captures k_l0 (launch #6)
    k_pos4<<<(BB*NPTS + 255)/256, 256>>>(pos);
    k_fps<<<BB, 1024, smF>>>(pos, octr, obat);
    k_zero<<<32, 256>>>();
    k_wprep<<<(3*2048 + 255)/256, 256>>>(W0, 67, 3, 0);
    k_nbr<<<BSZ, 128>>>();
    k_l0<<<NBLK, 128, smB>>>(x, b0);
    k_prep<<<1, 128>>>(g0, be0, 0);
    k_wprep<<<(4*2048 + 255)/256, 256>>>(W1, HID, 4, 1);
    k_l1<<<NBLK, 128, smB>>>(b1);
    k_prep<<<1, 128>>>(g1, be1, 1);
    k_wprep<<<(4*2048 + 255)/256, 256>>>(W2, HID, 4, 2);
    k_l2<<<NBLK, 128, smB>>>(b2, out);
}

// round 14
// speedup vs baseline: 3.3559x; 1.0538x over previous
#include <cuda_runtime.h>
#include <cuda_fp16.h>
#include <cstdint>
#include <cstddef>

#define BB   8
#define NPTS 4096
#define SS   2048
#define KNB  64
#define CIN  64
#define HID  128
#define BSZ  (BB*SS)
#define R2F  0.04f
#define MAXC 1024
#define NBLK (BSZ/2)          // 2 centroids per GEMM block
#define SROW 132              // fp32 staging row stride

// ---------------- device scratch ----------------
__device__ float  g_ctr[BSZ*3];
__device__ int    g_nbr[BSZ*KNB];
__device__ int    g_cnt[BSZ];
__device__ float4 g_pos4[BB*NPTS];
__device__ uint2  g_H0h[(size_t)NBLK*4096];   // fp16 H0 (4 halfs per uint2)
__device__ uint2  g_H1h[(size_t)NBLK*4096];   // fp16 H1
__device__ double g_stat[2][2][32][HID];      // 16384 doubles
__device__ float  g_scale[2][HID];
__device__ float  g_shift[2][HID];
// pair-fragment fp16 hi/lo weights: per slab 4096 u32 = [hi 2048 | lo 2048]
__device__ uint32_t g_WF0[3*4096];
__device__ uint32_t g_WF1[4*4096];
__device__ uint32_t g_WF2[4*4096];

// ---------------- helpers ----------------
__device__ __forceinline__ uint32_t smem_u32(const void* p) {
    uint32_t a;
    asm("{ .reg .u64 t; cvta.to.shared.u64 t, %1; cvt.u32.u64 %0, t; }" : "=r"(a) : "l"(p));
    return a;
}
__device__ __forceinline__ void cp16(void* dst, const void* src) {
    asm volatile("cp.async.ca.shared.global [%0], [%1], 16;"
                 :: "r"(smem_u32(dst)), "l"(src) : "memory");
}
#define CP_COMMIT() asm volatile("cp.async.commit_group;" ::: "memory")
#define CP_WAIT0()  asm volatile("cp.async.wait_group 0;" ::: "memory")

__device__ __forceinline__ uint32_t h2(float x, float y) {
    __half2 v = __floats2half2_rn(x, y);
    return *(uint32_t*)&v;
}

__device__ __forceinline__ void mma16(float* c, uint32_t a0, uint32_t a1, uint32_t a2,
                                      uint32_t a3, uint32_t b0, uint32_t b1) {
    asm volatile("mma.sync.aligned.m16n8k16.row.col.f32.f16.f16.f32 "
        "{%0,%1,%2,%3}, {%4,%5,%6,%7}, {%8,%9}, {%0,%1,%2,%3};\n"
        : "+f"(c[0]), "+f"(c[1]), "+f"(c[2]), "+f"(c[3])
        : "r"(a0), "r"(a1), "r"(a2), "r"(a3), "r"(b0), "r"(b1));
}

// GEMM slab: A' = fp16(A) single conversion; B pair-fragment hi/lo images.
// D += A'*Bh + A'*Bl
__device__ __forceinline__ void gemm_slab(const float* sA, const uint32_t* sB,
                                          float (*acc)[4], int w, int lane, int scol,
                                          int nkk) {
    int g = lane >> 2, tig = lane & 3;
#pragma unroll 1
    for (int kk = 0; kk < nkk; kk++) {
        uint32_t a[2][4];
#pragma unroll
        for (int rt = 0; rt < 2; rt++) {
            const float* base = sA + (32*w + 16*rt + g)*SROW + scol + kk*16 + 2*tig;
            float2 v00 = *(const float2*)(base);
            float2 v01 = *(const float2*)(base + 8);
            float2 v10 = *(const float2*)(base + 8*SROW);
            float2 v11 = *(const float2*)(base + 8*SROW + 8);
            a[rt][0] = h2(v00.x, v00.y);
            a[rt][1] = h2(v10.x, v10.y);
            a[rt][2] = h2(v01.x, v01.y);
            a[rt][3] = h2(v11.x, v11.y);
        }
        const uint32_t* bh = sB + kk*1024;
        const uint32_t* bl = sB + 2048 + kk*1024;
#pragma unroll
        for (int tth = 0; tth < 8; tth++) {
            uint4 b = *(const uint4*)&bh[(tth*32 + lane)*4];
            mma16(acc[2*tth],      a[0][0], a[0][1], a[0][2], a[0][3], b.x, b.y);
            mma16(acc[16+2*tth],   a[1][0], a[1][1], a[1][2], a[1][3], b.x, b.y);
            mma16(acc[2*tth+1],    a[0][0], a[0][1], a[0][2], a[0][3], b.z, b.w);
            mma16(acc[16+2*tth+1], a[1][0], a[1][1], a[1][2], a[1][3], b.z, b.w);
        }
#pragma unroll
        for (int tth = 0; tth < 8; tth++) {
            uint4 b = *(const uint4*)&bl[(tth*32 + lane)*4];
            mma16(acc[2*tth],      a[0][0], a[0][1], a[0][2], a[0][3], b.x, b.y);
            mma16(acc[16+2*tth],   a[1][0], a[1][1], a[1][2], a[1][3], b.x, b.y);
            mma16(acc[2*tth+1],    a[0][0], a[0][1], a[0][2], a[0][3], b.z, b.w);
            mma16(acc[16+2*tth+1], a[1][0], a[1][1], a[1][2], a[1][3], b.z, b.w);
        }
    }
}

// async B slab copy (each thread 8x uint4)
__device__ __forceinline__ void stageB(uint32_t* buf, const uint32_t* src, int t) {
#pragma unroll
    for (int i = 0; i < 8; i++) {
        int idx = (t + i*128) * 4;
        cp16(buf + idx, src + idx);
    }
    CP_COMMIT();
}

// acc -> (+bias) -> staging rows (warp writes only its own rows)
__device__ __forceinline__ void epi_to_stage(float* sA, float (*acc)[4], const float* bias,
                                             int w, int lane) {
    int g = lane >> 2, tig = lane & 3;
#pragma unroll
    for (int rt = 0; rt < 2; rt++)
#pragma unroll
        for (int tt = 0; tt < 16; tt++) {
            int n0 = tt*8 + tig*2;
            float bz0 = bias[n0], bz1 = bias[n0+1];
            float* r0 = sA + (32*w + 16*rt + g)*SROW + n0;
            const float* a = acc[rt*16 + tt];
            *(float2*)r0            = make_float2(a[0]+bz0, a[1]+bz1);
            *(float2*)(r0 + 8*SROW) = make_float2(a[2]+bz0, a[3]+bz1);
        }
}

// staging -> fp16 global H
__device__ __forceinline__ void stage_to_H(uint2* dstH, const float* sA, int t) {
    for (int i = t; i < 4096; i += 128) {
        const float* s = sA + (i >> 5)*SROW + (i & 31)*4;
        __half2 h0 = __floats2half2_rn(s[0], s[1]);
        __half2 h1 = __floats2half2_rn(s[2], s[3]);
        uint2 u;
        u.x = *(uint32_t*)&h0;
        u.y = *(uint32_t*)&h1;
        dstH[i] = u;
    }
}

// fp16 global H -> bn+relu -> fp32 staging
__device__ __forceinline__ void H_to_stage(float* sA, const uint2* src, int t,
                                           const float* sc, const float* sh) {
    for (int i = t; i < 4096; i += 128) {
        int row = i >> 5, c4 = (i & 31) * 4;
        uint2 u = src[i];
        float2 f0 = __half22float2(*(__half2*)&u.x);
        float2 f1 = __half22float2(*(__half2*)&u.y);
        float4 z;
        z.x = fmaxf(0.f, fmaf(f0.x, sc[c4+0], sh[c4+0]));
        z.y = fmaxf(0.f, fmaf(f0.y, sc[c4+1], sh[c4+1]));
        z.z = fmaxf(0.f, fmaf(f1.x, sc[c4+2], sh[c4+2]));
        z.w = fmaxf(0.f, fmaf(f1.y, sc[c4+3], sh[c4+3]));
        *(float4*)(sA + row*SROW + c4) = z;
    }
}

// ---------------- weight fragment prep item (fp16 hi/lo, paired tt layout) ----------------
__device__ __forceinline__ void wprep_item(const float* __restrict__ W, int K,
                                           uint32_t* dst, int i) {
    int s = i >> 11, r = i & 2047;
    int q = r & 3, lane = (r >> 2) & 31, tth = (r >> 7) & 7, kk = (r >> 10) & 1;
    int reg = q & 1, tto = q >> 1;
    int tt = tth*2 + tto;
    int k0 = s*32 + kk*16 + reg*8 + (lane & 3)*2;
    int n  = tt*8 + (lane >> 2);
    float v0 = (k0     < K) ? W[k0*HID + n]     : 0.f;
    float v1 = (k0 + 1 < K) ? W[(k0+1)*HID + n] : 0.f;
    __half2 hh = __floats2half2_rn(v0, v1);
    float l0 = v0 - __half2float(__low2half(hh));
    float l1 = v1 - __half2float(__high2half(hh));
    dst[s*4096 + r]        = *(uint32_t*)&hh;
    dst[s*4096 + 2048 + r] = h2(l0, l1);
}

// ---------------- merged prep: pos4 + stat-zero + wprep x3 ----------------
// ranges: [0,32768) pos4 | [32768,49152) zero ALL 16384 stat doubles
//         [49152,55296) W0 | [55296,63488) W1 | [63488,71680) W2
__global__ void k_prep0(const float* __restrict__ pos,
                        const float* __restrict__ W0,
                        const float* __restrict__ W1,
                        const float* __restrict__ W2) {
    int i = blockIdx.x * blockDim.x + threadIdx.x;
    if (i < 32768) {
        g_pos4[i] = make_float4(pos[3*i], pos[3*i+1], pos[3*i+2], 0.f);
    } else if (i < 49152) {
        (&g_stat[0][0][0][0])[i - 32768] = 0.0;
    } else if (i < 55296) {
        wprep_item(W0, 67, g_WF0, i - 49152);
    } else if (i < 63488) {
        wprep_item(W1, HID, g_WF1, i - 55296);
    } else if (i < 71680) {
        wprep_item(W2, HID, g_WF2, i - 63488);
    }
}

// ---------------- farthest point sampling (1 sync/iter, smem coords) ----------------
__global__ void __launch_bounds__(1024) k_fps(const float* __restrict__ pos,
                                              float* __restrict__ octr,
                                              float* __restrict__ obat) {
    extern __shared__ float fs[];    // sx[4096], sy[4096], sz[4096]
    float* sx = fs;
    float* sy = fs + NPTS;
    float* sz = fs + 2*NPTS;
    int b = blockIdx.x, t = threadIdx.x;
    const float* p = pos + (size_t)b * NPTS * 3;
    float px[4], py[4], pz[4], md[4];
#pragma unroll
    for (int j = 0; j < 4; j++) {
        int i = t + j * 1024;
        px[j] = p[3*i]; py[j] = p[3*i+1]; pz[j] = p[3*i+2];
        sx[i] = px[j]; sy[i] = py[j]; sz[i] = pz[j];
        md[j] = __int_as_float(0x7f800000);
    }
    __shared__ unsigned svk[2][32];
    __shared__ unsigned svi[2][32];
    int lane = t & 31, w = t >> 5;
    int last = 0;
    __syncthreads();
    for (int s = 0; s < SS; s++) {
        float qx = sx[last], qy = sy[last], qz = sz[last];
        if (t == 0) {
            int o = b*SS + s;
            g_ctr[o*3] = qx; g_ctr[o*3+1] = qy; g_ctr[o*3+2] = qz;
            if (octr) { octr[o*3] = qx; octr[o*3+1] = qy; octr[o*3+2] = qz; }
            if (obat) obat[o] = (float)b;
        }
        float bv = -1.f; int bi = 0;
#pragma unroll
        for (int j = 0; j < 4; j++) {
            float dx = px[j]-qx, dy = py[j]-qy, dz = pz[j]-qz;
            float d = fmaf(dz, dz, fmaf(dy, dy, __fmul_rn(dx, dx)));
            md[j] = fminf(md[j], d);
            if (md[j] > bv) { bv = md[j]; bi = t + j*1024; }  // strict >: lowest idx wins
        }
        unsigned key  = __float_as_uint(bv);
        unsigned vmax = __reduce_max_sync(0xffffffffu, key);
        unsigned cand = (key == vmax) ? (unsigned)bi : 0xffffffffu;
        unsigned imin = __reduce_min_sync(0xffffffffu, cand);
        int buf = s & 1;
        if (lane == 0) { svk[buf][w] = vmax; svi[buf][w] = imin; }
        __syncthreads();
        unsigned k2 = svk[buf][lane], i2 = svi[buf][lane];
        unsigned vm2 = __reduce_max_sync(0xffffffffu, k2);
        unsigned c2  = (k2 == vm2) ? i2 : 0xffffffffu;
        last = (int)__reduce_min_sync(0xffffffffu, c2);
    }
}

// ---------------- radius-capped kNN (known-good) ----------------
__global__ void __launch_bounds__(128) k_nbr() {
    int c = blockIdx.x, t = threadIdx.x;
    int b = c >> 11;
    __shared__ float sd[MAXC];
    __shared__ int   sid[MAXC];
    __shared__ int   hist[128];
    __shared__ int   sc, so, s_tb, s_m, tc;
    __shared__ float td[256];
    __shared__ int   tdi[256];
    __shared__ int   wtot[4];
    if (t == 0) { sc = 0; so = 0; tc = 0; }
    hist[t] = 0;
    float cx = g_ctr[c*3], cy = g_ctr[c*3+1], cz = g_ctr[c*3+2];
    __syncthreads();
    for (int i = t; i < NPTS; i += 128) {
        float4 P = g_pos4[b*NPTS + i];
        float dx = P.x-cx, dy = P.y-cy, dz = P.z-cz;
        float d = fmaf(dz, dz, fmaf(dy, dy, __fmul_rn(dx, dx)));
        if (d <= R2F) {
            int k = atomicAdd(&sc, 1);
            if (k < MAXC) { sd[k] = d; sid[k] = i; }
        }
    }
    __syncthreads();
    int cnt = min(sc, MAXC);
    if (cnt <= KNB) {
        if (t < cnt) g_nbr[c*KNB + t] = sid[t];
        if (t == 0) g_cnt[c] = cnt;
        return;
    }
    const float bsc = 128.0f / R2F;
    for (int i = t; i < cnt; i += 128) {
        int bk = min(127, (int)(sd[i] * bsc));
        atomicAdd(&hist[bk], 1);
    }
    __syncthreads();
    {
        int lane = t & 31, w = t >> 5;
        int h = hist[t], v = h;
#pragma unroll
        for (int o = 1; o < 32; o <<= 1) {
            int u = __shfl_up_sync(0xffffffffu, v, o);
            if (lane >= o) v += u;
        }
        if (lane == 31) wtot[w] = v;
        __syncthreads();
        int base = 0;
        for (int k2 = 0; k2 < w; k2++) base += wtot[k2];
        int incl = v + base, excl = incl - h;
        if (incl >= KNB && excl < KNB) { s_tb = t; s_m = excl; }
    }
    __syncthreads();
    int tb = s_tb, m = s_m;
    for (int i = t; i < cnt; i += 128) {
        int bk = min(127, (int)(sd[i] * bsc));
        if (bk < tb) {
            int k = atomicAdd(&so, 1);
            g_nbr[c*KNB + k] = sid[i];
        } else if (bk == tb) {
            int k = atomicAdd(&tc, 1);
            if (k < 256) { td[k] = sd[i]; tdi[k] = sid[i]; }
        }
    }
    __syncthreads();
    int bn = min(tc, 256), rem = KNB - m;
    for (int i = t; i < bn; i += 128) {
        float di = td[i]; int ii = tdi[i];
        int rank = 0;
        for (int j2 = 0; j2 < bn; j2++) {
            float dj = td[j2]; int ij = tdi[j2];
            if (dj < di || (dj == di && ij < ii)) rank++;
        }
        if (rank < rem) {
            int k = atomicAdd(&so, 1);
            g_nbr[c*KNB + k] = tdi[i];
        }
    }
    if (t == 0) g_cnt[c] = KNB;
}

// ---------------- layer 0: gather -> GEMM -> H0(fp16) + stats ----------------
__global__ void __launch_bounds__(128, 2) k_l0(const float* __restrict__ x,
                                               const float* __restrict__ b0) {
    extern __shared__ float sm[];
    float*    sA   = sm;                         // 128*132 f32
    uint32_t* sB0  = (uint32_t*)(sm + 128*SROW); // 4096 u32
    uint32_t* sB1  = sB0 + 4096;
    float*    bias = sm + 128*SROW + 8192;       // 128
    int t = threadIdx.x, w = t >> 5, lane = t & 31, blk = blockIdx.x;
    bias[t] = b0[t];

    stageB(sB0, g_WF0, t);   // slab 0 in flight

    // own-row gather: thread t fills row t cols 0..79 (rest never read in L0)
    int c2 = blk*2 + (t >> 6), e = t & 63;
    int cnt_my = g_cnt[c2];
    float* row = sA + t*SROW;
    float4 z4 = make_float4(0.f, 0.f, 0.f, 0.f);
    if (e < cnt_my) {
        int j = g_nbr[c2*KNB + e];
        int bcl = c2 >> 11;
        const float4* xr = (const float4*)(x + (size_t)(bcl*NPTS + j)*CIN);
#pragma unroll
        for (int q = 0; q < 16; q++)
            *(float4*)(row + 4*q) = xr[q];
        float4 P = g_pos4[bcl*NPTS + j];
        row[64] = P.x - g_ctr[c2*3];
        row[65] = P.y - g_ctr[c2*3+1];
        row[66] = P.z - g_ctr[c2*3+2];
        row[67] = 0.f;
        *(float4*)(row + 68) = z4;
        *(float4*)(row + 72) = z4;
        *(float4*)(row + 76) = z4;
    } else {
#pragma unroll
        for (int q = 0; q < 20; q++)
            *(float4*)(row + 4*q) = z4;
    }

    float acc[32][4];
#pragma unroll
    for (int i = 0; i < 32; i++)
#pragma unroll
        for (int r = 0; r < 4; r++) acc[i][r] = 0.f;

    uint32_t* bufs[2] = { sB0, sB1 };
#pragma unroll 1
    for (int s = 0; s < 3; s++) {
        CP_WAIT0();
        __syncthreads();
        if (s + 1 < 3) stageB(bufs[(s+1)&1], g_WF0 + (s+1)*4096, t);
        gemm_slab(sA, bufs[s&1], acc, w, lane, s*32, (s < 2) ? 2 : 1);
    }

    epi_to_stage(sA, acc, bias, w, lane);
    __syncthreads();

    stage_to_H(g_H0h + (size_t)blk * 4096, sA, t);

    int cnt0 = g_cnt[blk*2], cnt1 = g_cnt[blk*2+1];
    float ssum = 0.f, ssq = 0.f;
    for (int r = 0; r < 128; r++) {
        bool val = (r & 63) < ((r >> 6) ? cnt1 : cnt0);
        float v = sA[r*SROW + t];
        if (val) { ssum += v; ssq = fmaf(v, v, ssq); }
    }
    atomicAdd(&g_stat[0][0][blk & 31][t], (double)ssum);
    atomicAdd(&g_stat[0][1][blk & 31][t], (double)ssq);
}

// ---------------- bn prepare ----------------
__global__ void k_prep(const float* __restrict__ gamma,
                       const float* __restrict__ beta, int layer) {
    int t = threadIdx.x;
    int local = 0;
    for (int i = t; i < BSZ; i += 128) local += g_cnt[i];
    __shared__ int sred[4];
    int lane = t & 31, w = t >> 5;
#pragma unroll
    for (int off = 16; off > 0; off >>= 1)
        local += __shfl_down_sync(0xffffffffu, local, off);
    if (lane == 0) sred[w] = local;
    __syncthreads();
    double cntd = (double)(sred[0] + sred[1] + sred[2] + sred[3]);
    double s = 0.0, q = 0.0;
    for (int k = 0; k < 32; k++) {
        s += g_stat[layer][0][k][t];
        q += g_stat[layer][1][k][t];
    }
    double mean = s / cntd;
    double var = q / cntd - mean * mean;
    if (var < 0.0) var = 0.0;
    double a = (double)gamma[t] * rsqrt(var + 1e-5);
    g_scale[layer][t] = (float)a;
    g_shift[layer][t] = (float)((double)beta[t] - mean * a);
}

// ---------------- layer 1: bnrelu(H0) -> GEMM -> H1(fp16) + stats ----------------
__global__ void __launch_bounds__(128, 2) k_l1(const float* __restrict__ b1) {
    extern __shared__ float sm[];
    float*    sA   = sm;
    uint32_t* sB0  = (uint32_t*)(sm + 128*SROW);
    uint32_t* sB1  = sB0 + 4096;
    float*    bias = sm + 128*SROW + 8192;
    float*    sc   = bias + 128;
    float*    sh   = sc + 128;
    int t = threadIdx.x, w = t >> 5, lane = t & 31, blk = blockIdx.x;
    bias[t] = b1[t]; sc[t] = g_scale[0][t]; sh[t] = g_shift[0][t];

    stageB(sB0, g_WF1, t);
    __syncthreads();   // sc/sh visible for staging below

    H_to_stage(sA, g_H0h + (size_t)blk * 4096, t, sc, sh);

    float acc[32][4];
#pragma unroll
    for (int i = 0; i < 32; i++)
#pragma unroll
        for (int r = 0; r < 4; r++) acc[i][r] = 0.f;

    uint32_t* bufs[2] = { sB0, sB1 };
#pragma unroll 1
    for (int s = 0; s < 4; s++) {
        CP_WAIT0();
        __syncthreads();
        if (s + 1 < 4) stageB(bufs[(s+1)&1], g_WF1 + (s+1)*4096, t);
        gemm_slab(sA, bufs[s&1], acc, w, lane, s*32, 2);
    }

    epi_to_stage(sA, acc, bias, w, lane);
    __syncthreads();

    stage_to_H(g_H1h + (size_t)blk * 4096, sA, t);

    int cnt0 = g_cnt[blk*2], cnt1 = g_cnt[blk*2+1];
    float ssum = 0.f, ssq = 0.f;
    for (int r = 0; r < 128; r++) {
        bool val = (r & 63) < ((r >> 6) ? cnt1 : cnt0);
        float v = sA[r*SROW + t];
        if (val) { ssum += v; ssq = fmaf(v, v, ssq); }
    }
    atomicAdd(&g_stat[1][0][blk & 31][t], (double)ssum);
    atomicAdd(&g_stat[1][1][blk & 31][t], (double)ssq);
}

// ---------------- layer 2: bnrelu(H1) -> GEMM -> masked max -> out ----------------
__global__ void __launch_bounds__(128, 2) k_l2(const float* __restrict__ b2,
                                               float* __restrict__ outp) {
    extern __shared__ float sm[];
    float*    sA   = sm;
    uint32_t* sB0  = (uint32_t*)(sm + 128*SROW);
    uint32_t* sB1  = sB0 + 4096;
    float*    bias = sm + 128*SROW + 8192;
    float*    sc   = bias + 128;
    float*    sh   = sc + 128;
    int t = threadIdx.x, w = t >> 5, lane = t & 31, blk = blockIdx.x;
    bias[t] = b2[t]; sc[t] = g_scale[1][t]; sh[t] = g_shift[1][t];

    stageB(sB0, g_WF2, t);
    __syncthreads();

    H_to_stage(sA, g_H1h + (size_t)blk * 4096, t, sc, sh);

    float acc[32][4];
#pragma unroll
    for (int i = 0; i < 32; i++)
#pragma unroll
        for (int r = 0; r < 4; r++) acc[i][r] = 0.f;

    uint32_t* bufs[2] = { sB0, sB1 };
#pragma unroll 1
    for (int s = 0; s < 4; s++) {
        CP_WAIT0();
        __syncthreads();
        if (s + 1 < 4) stageB(bufs[(s+1)&1], g_WF2 + (s+1)*4096, t);
        gemm_slab(sA, bufs[s&1], acc, w, lane, s*32, 2);
    }

    epi_to_stage(sA, acc, bias, w, lane);
    __syncthreads();

    int cnt0 = g_cnt[blk*2], cnt1 = g_cnt[blk*2+1];
    const float NINF = __int_as_float(0xff800000);
    float m0 = NINF, m1 = NINF;
    for (int r = 0; r < 64; r++)
        if (r < cnt0) m0 = fmaxf(m0, sA[r*SROW + t]);
    for (int r = 64; r < 128; r++)
        if ((r - 64) < cnt1) m1 = fmaxf(m1, sA[r*SROW + t]);
    outp[(size_t)(blk*2)     * HID + t] = m0;
    outp[(size_t)(blk*2 + 1) * HID + t] = m1;
}

// ---------------- launch ----------------
extern "C" void kernel_launch(void* const* d_in, const int* in_sizes, int n_in,
                              void* d_out, int out_size) {
    const float* x   = (const float*)d_in[0];
    const float* pos = (const float*)d_in[1];
    const float* W0  = (const float*)d_in[3];
    const float* b0  = (const float*)d_in[4];
    const float* g0  = (const float*)d_in[5];
    const float* be0 = (const float*)d_in[6];
    const float* W1  = (const float*)d_in[7];
    const float* b1  = (const float*)d_in[8];
    const float* g1  = (const float*)d_in[9];
    const float* be1 = (const float*)d_in[10];
    const float* W2  = (const float*)d_in[11];
    const float* b2  = (const float*)d_in[12];
    float* out = (float*)d_out;

    float* octr = (out_size >= BSZ*HID + BSZ*3) ? out + (size_t)BSZ*HID : nullptr;
    float* obat = (out_size >= BSZ*HID + BSZ*3 + BSZ) ? out + (size_t)BSZ*131 : nullptr;

    int smB = (128*SROW + 8192 + 384) * 4;   // 101,888 B
    int smF = 3 * NPTS * 4;                  // 49,152 B
    cudaFuncSetAttribute(k_l0, cudaFuncAttributeMaxDynamicSharedMemorySize, smB);
    cudaFuncSetAttribute(k_l1, cudaFuncAttributeMaxDynamicSharedMemorySize, smB);
    cudaFuncSetAttribute(k_l2, cudaFuncAttributeMaxDynamicSharedMemorySize, smB);
    cudaFuncSetAttribute(k_fps, cudaFuncAttributeMaxDynamicSharedMemorySize, smF);

    // launch order: l0 is launch #4 (= ncu capture slot 6 with the 2 harness launches)
    k_prep0<<<(71680 + 255)/256, 256>>>(pos, W0, W1, W2);
    k_fps<<<BB, 1024, smF>>>(pos, octr, obat);
    k_nbr<<<BSZ, 128>>>();
    k_l0<<<NBLK, 128, smB>>>(x, b0);
    k_prep<<<1, 128>>>(g0, be0, 0);
    k_l1<<<NBLK, 128, smB>>>(b1);
    k_prep<<<1, 128>>>(g1, be1, 1);
    k_l2<<<NBLK, 128, smB>>>(b2, out);
}